// round 6
// baseline (speedup 1.0000x reference)
#include <cuda_runtime.h>
#include <math.h>

#define BB 2
#define SS 2048
#define DD 2048
#define HH 16
#define DH 128

// Scratch (no allocations allowed)
__device__ float g_q[(size_t)BB * SS * HH * DH];     // 32 MB  [b,s,h,d]
__device__ float g_kv[(size_t)BB * SS * 2 * DH];     //  4 MB  [b,s, k(128)|v(128)]
__device__ float g_attn[(size_t)BB * SS * HH * DH];  // 32 MB  [b,s,h,d]
__device__ float g_rope[SS * DH];                    // 1 MB   [s][p]=cos, [s][p+64]=sin

// ---------------------------------------------------------------------------
// Build RoPE table: for s in [0,SS), p in [0,64):
//   g_rope[s*128 + p]      = cos(s * 10000^(-2p/128))
//   g_rope[s*128 + p + 64] = sin(...)
// Double-precision trig: angles reach 2047 rad; fast-math range reduction
// would blow the 1e-3 budget.
// ---------------------------------------------------------------------------
__global__ void rope_table_kernel()
{
    int idx = blockIdx.x * blockDim.x + threadIdx.x;   // 0 .. SS*64-1
    if (idx >= SS * 64) return;
    int s = idx >> 6;
    int p = idx & 63;
    double inv = pow(10000.0, -((double)(2 * p)) / 128.0);
    double ang = (double)s * inv;
    g_rope[s * DH + p]      = (float)cos(ang);
    g_rope[s * DH + p + 64] = (float)sin(ang);
}

// Apply RoPE in-place. For q: n_rows=B*S*H, stride=128, s_div=H.
// For k: n_rows=B*S, stride=256, s_div=1.
__global__ void rope_apply_kernel(float* __restrict__ buf, int n_rows,
                                  int row_stride, int s_div)
{
    int idx = blockIdx.x * blockDim.x + threadIdx.x;
    if (idx >= n_rows * 64) return;
    int r = idx >> 6;
    int p = idx & 63;
    int s = (r / s_div) % SS;
    float c  = g_rope[s * DH + p];
    float sn = g_rope[s * DH + p + 64];
    float* row = buf + (size_t)r * row_stride;
    float a  = row[p];
    float b2 = row[p + 64];
    row[p]      = a * c - b2 * sn;
    row[p + 64] = b2 * c + a * sn;
}

// ---------------------------------------------------------------------------
// C[M,N] = A[M,K] @ W[N,K]^T + bias[N]      (row-major A and W)
// 128x128x16 tiles, 8x8 per-thread register tile, 256 threads.
// Requires M%128==0, N%128==0, K%16==0 (true for all three uses).
// ---------------------------------------------------------------------------
__global__ void __launch_bounds__(256)
sgemm_bias(const float* __restrict__ A, const float* __restrict__ W,
           const float* __restrict__ bias, float* __restrict__ C,
           int M, int N, int K)
{
    const int BM = 128, BN = 128, BK = 16, TM = 8, TN = 8;
    __shared__ float As[BK * BM];
    __shared__ float Bs[BK * BN];

    int tid = threadIdx.x;
    int tr = tid >> 4;        // 0..15 : row group
    int tc = tid & 15;        // 0..15 : col group
    int m0 = blockIdx.y * BM;
    int n0 = blockIdx.x * BN;

    float acc[TM][TN];
#pragma unroll
    for (int i = 0; i < TM; i++)
#pragma unroll
        for (int j = 0; j < TN; j++) acc[i][j] = 0.f;

    for (int k0 = 0; k0 < K; k0 += BK) {
#pragma unroll
        for (int t = 0; t < 2; t++) {
            int idx = tid + t * 256;        // 0..511 float4 slots
            int row = idx >> 2;             // 0..127
            int c4  = (idx & 3) << 2;       // 0,4,8,12
            float4 va = *(const float4*)&A[(size_t)(m0 + row) * K + k0 + c4];
            As[(c4 + 0) * BM + row] = va.x;
            As[(c4 + 1) * BM + row] = va.y;
            As[(c4 + 2) * BM + row] = va.z;
            As[(c4 + 3) * BM + row] = va.w;
            float4 vb = *(const float4*)&W[(size_t)(n0 + row) * K + k0 + c4];
            Bs[(c4 + 0) * BN + row] = vb.x;
            Bs[(c4 + 1) * BN + row] = vb.y;
            Bs[(c4 + 2) * BN + row] = vb.z;
            Bs[(c4 + 3) * BN + row] = vb.w;
        }
        __syncthreads();

#pragma unroll
        for (int k = 0; k < BK; k++) {
            float ra[TM], rb[TN];
            *(float4*)&ra[0] = *(const float4*)&As[k * BM + tr * TM];
            *(float4*)&ra[4] = *(const float4*)&As[k * BM + tr * TM + 4];
            *(float4*)&rb[0] = *(const float4*)&Bs[k * BN + tc * TN];
            *(float4*)&rb[4] = *(const float4*)&Bs[k * BN + tc * TN + 4];
#pragma unroll
            for (int i = 0; i < TM; i++)
#pragma unroll
                for (int j = 0; j < TN; j++)
                    acc[i][j] += ra[i] * rb[j];
        }
        __syncthreads();
    }

    float bv[TN];
    *(float4*)&bv[0] = *(const float4*)&bias[n0 + tc * TN];
    *(float4*)&bv[4] = *(const float4*)&bias[n0 + tc * TN + 4];
#pragma unroll
    for (int i = 0; i < TM; i++) {
        float* crow = &C[(size_t)(m0 + tr * TM + i) * N + n0 + tc * TN];
#pragma unroll
        for (int j = 0; j < TN; j += 4) {
            float4 v;
            v.x = acc[i][j + 0] + bv[j + 0];
            v.y = acc[i][j + 1] + bv[j + 1];
            v.z = acc[i][j + 2] + bv[j + 2];
            v.w = acc[i][j + 3] + bv[j + 3];
            *(float4*)&crow[j] = v;
        }
    }
}

// ---------------------------------------------------------------------------
// Causal flash attention (MQA: one KV head shared by all 16 Q heads).
// BM=64 queries, BN=64 keys per tile, 256 threads (16x16), online softmax.
// smem: Qts[128][64] + Kts[128][64] (d-major, conflict-free LDS.128),
//       Vs[64][128], Ps[64][64]  -> 112 KB dynamic.
// ---------------------------------------------------------------------------
__global__ void __launch_bounds__(256)
attn_kernel(const float* __restrict__ Q, const float* __restrict__ KV,
            float* __restrict__ O)
{
    extern __shared__ float sm[];
    float* Qts = sm;                 // [d][r]  128*64
    float* Kts = Qts + 128 * 64;     // [d][r]  128*64
    float* Vs  = Kts + 128 * 64;     // [r][d]  64*128
    float* Ps  = Vs  + 64 * 128;     // [r][c]  64*64

    int qt  = blockIdx.x;            // 0..31
    int h   = blockIdx.y;
    int b   = blockIdx.z;
    int tid = threadIdx.x;
    int ty  = tid >> 4;              // 0..15 : query-row group (4 rows)
    int tx  = tid & 15;              // 0..15 : col group
    int q0  = qt * 64;
    const float scale = 0.08838834764831845f;  // 1/sqrt(128)

    // Load Q tile transposed: (row r, dim d) -> Qts[d*64 + r]
    size_t qbase = (((size_t)b * SS + q0) * HH + h) * DH;
#pragma unroll
    for (int t = 0; t < 8; t++) {
        int f  = tid + t * 256;          // 0..2047 float4s
        int r  = f >> 5;                 // 0..63
        int d4 = (f & 31) << 2;          // 0..124
        float4 v = *(const float4*)&Q[qbase + (size_t)r * (HH * DH) + d4];
        Qts[(d4 + 0) * 64 + r] = v.x;
        Qts[(d4 + 1) * 64 + r] = v.y;
        Qts[(d4 + 2) * 64 + r] = v.z;
        Qts[(d4 + 3) * 64 + r] = v.w;
    }

    float acc[4][8];
#pragma unroll
    for (int i = 0; i < 4; i++)
#pragma unroll
        for (int c = 0; c < 8; c++) acc[i][c] = 0.f;
    float run_max[4] = {-1e30f, -1e30f, -1e30f, -1e30f};
    float run_sum[4] = {0.f, 0.f, 0.f, 0.f};

    for (int kt = 0; kt <= qt; kt++) {
        int k0 = kt * 64;
        size_t kvbase = ((size_t)b * SS + k0) * (2 * DH);
#pragma unroll
        for (int t = 0; t < 8; t++) {
            int f  = tid + t * 256;
            int r  = f >> 5;
            int d4 = (f & 31) << 2;
            float4 kv4 = *(const float4*)&KV[kvbase + (size_t)r * (2 * DH) + d4];
            Kts[(d4 + 0) * 64 + r] = kv4.x;
            Kts[(d4 + 1) * 64 + r] = kv4.y;
            Kts[(d4 + 2) * 64 + r] = kv4.z;
            Kts[(d4 + 3) * 64 + r] = kv4.w;
            float4 vv = *(const float4*)&KV[kvbase + (size_t)r * (2 * DH) + DH + d4];
            *(float4*)&Vs[r * 128 + d4] = vv;
        }
        __syncthreads();

        // S tile: s_[i][j] = q(ty*4+i) . k(tx*4+j)
        float s_[4][4];
#pragma unroll
        for (int i = 0; i < 4; i++)
#pragma unroll
            for (int j = 0; j < 4; j++) s_[i][j] = 0.f;

#pragma unroll 4
        for (int d = 0; d < 128; d++) {
            float4 rq = *(const float4*)&Qts[d * 64 + ty * 4];
            float4 rk = *(const float4*)&Kts[d * 64 + tx * 4];
            float qa[4] = {rq.x, rq.y, rq.z, rq.w};
            float ka[4] = {rk.x, rk.y, rk.z, rk.w};
#pragma unroll
            for (int i = 0; i < 4; i++)
#pragma unroll
                for (int j = 0; j < 4; j++)
                    s_[i][j] += qa[i] * ka[j];
        }

        // Mask + scale + online softmax (row reduction across 16-lane groups)
#pragma unroll
        for (int i = 0; i < 4; i++) {
            int qg = q0 + ty * 4 + i;
            float m = -1e30f;
#pragma unroll
            for (int j = 0; j < 4; j++) {
                int kg = k0 + tx * 4 + j;
                float val = (kg <= qg) ? s_[i][j] * scale : -1e9f;
                s_[i][j] = val;
                m = fmaxf(m, val);
            }
#pragma unroll
            for (int off = 8; off > 0; off >>= 1)
                m = fmaxf(m, __shfl_xor_sync(0xffffffffu, m, off, 16));
            float mn = fmaxf(run_max[i], m);
            float f = __expf(run_max[i] - mn);
            run_max[i] = mn;
            float4 p;
            p.x = __expf(s_[i][0] - mn);
            p.y = __expf(s_[i][1] - mn);
            p.z = __expf(s_[i][2] - mn);
            p.w = __expf(s_[i][3] - mn);
            float lsum = p.x + p.y + p.z + p.w;
#pragma unroll
            for (int off = 8; off > 0; off >>= 1)
                lsum += __shfl_xor_sync(0xffffffffu, lsum, off, 16);
            run_sum[i] = run_sum[i] * f + lsum;
#pragma unroll
            for (int c = 0; c < 8; c++) acc[i][c] *= f;
            *(float4*)&Ps[(ty * 4 + i) * 64 + tx * 4] = p;
        }
        __syncthreads();

        // O += P @ V   (rows ty*4+i, cols tx*8..tx*8+7)
#pragma unroll 4
        for (int n = 0; n < 64; n++) {
            float4 rv0 = *(const float4*)&Vs[n * 128 + tx * 8];
            float4 rv1 = *(const float4*)&Vs[n * 128 + tx * 8 + 4];
#pragma unroll
            for (int i = 0; i < 4; i++) {
                float rp = Ps[(ty * 4 + i) * 64 + n];
                acc[i][0] += rp * rv0.x;
                acc[i][1] += rp * rv0.y;
                acc[i][2] += rp * rv0.z;
                acc[i][3] += rp * rv0.w;
                acc[i][4] += rp * rv1.x;
                acc[i][5] += rp * rv1.y;
                acc[i][6] += rp * rv1.z;
                acc[i][7] += rp * rv1.w;
            }
        }
        __syncthreads();
    }

    // Epilogue: normalize and store [b,s,h,d]
#pragma unroll
    for (int i = 0; i < 4; i++) {
        float inv = 1.f / run_sum[i];
        int qg = q0 + ty * 4 + i;
        size_t obase = (((size_t)b * SS + qg) * HH + h) * DH + tx * 8;
        float4 v0, v1;
        v0.x = acc[i][0] * inv; v0.y = acc[i][1] * inv;
        v0.z = acc[i][2] * inv; v0.w = acc[i][3] * inv;
        v1.x = acc[i][4] * inv; v1.y = acc[i][5] * inv;
        v1.z = acc[i][6] * inv; v1.w = acc[i][7] * inv;
        *(float4*)&O[obase]     = v0;
        *(float4*)&O[obase + 4] = v1;
    }
}

// ---------------------------------------------------------------------------
extern "C" void kernel_launch(void* const* d_in, const int* in_sizes, int n_in,
                              void* d_out, int out_size)
{
    const float* x   = (const float*)d_in[0];
    const float* qw  = (const float*)d_in[1];
    const float* qb  = (const float*)d_in[2];
    const float* kvw = (const float*)d_in[3];
    const float* kvb = (const float*)d_in[4];
    const float* ow  = (const float*)d_in[5];
    const float* ob  = (const float*)d_in[6];
    float* out = (float*)d_out;

    float *q_buf, *kv_buf, *attn_buf;
    cudaGetSymbolAddress((void**)&q_buf, g_q);
    cudaGetSymbolAddress((void**)&kv_buf, g_kv);
    cudaGetSymbolAddress((void**)&attn_buf, g_attn);

    const int M = BB * SS;   // 4096

    // 0) RoPE cos/sin table (cheap; recomputed every call for determinism)
    rope_table_kernel<<<(SS * 64 + 255) / 256, 256>>>();

    // 1) Q projection: [4096,2048] = x @ qw^T + qb
    sgemm_bias<<<dim3(DD / 128, M / 128), 256>>>(x, qw, qb, q_buf, M, DD, DD);

    // 2) KV projection: [4096,256] = x @ kvw^T + kvb
    sgemm_bias<<<dim3(256 / 128, M / 128), 256>>>(x, kvw, kvb, kv_buf, M, 256, DD);

    // 3) RoPE on q and k
    {
        int nq = BB * SS * HH * 64;
        rope_apply_kernel<<<(nq + 255) / 256, 256>>>(q_buf, BB * SS * HH, DH, HH);
        int nk = BB * SS * 64;
        rope_apply_kernel<<<(nk + 255) / 256, 256>>>(kv_buf, BB * SS, 2 * DH, 1);
    }

    // 4) Causal MQA flash attention
    {
        const int SMEM = (128 * 64 + 128 * 64 + 64 * 128 + 64 * 64) * sizeof(float); // 114688
        cudaFuncSetAttribute(attn_kernel, cudaFuncAttributeMaxDynamicSharedMemorySize, SMEM);
        attn_kernel<<<dim3(SS / 64, HH, BB), 256, SMEM>>>(q_buf, kv_buf, attn_buf);
    }

    // 5) Output projection: out = attn @ ow^T + ob
    sgemm_bias<<<dim3(DD / 128, M / 128), 256>>>(attn_buf, ow, ob, out, M, DD, DD);
}

// round 10
// speedup vs baseline: 1.3309x; 1.3309x over previous
#include <cuda_runtime.h>
#include <cuda_bf16.h>
#include <math.h>
#include <stdint.h>

#define BB 2
#define SS 2048
#define DD 2048
#define HH 16
#define DH 128

// ===========================================================================
// Helpers (base-ISA only: ldmatrix + mma.sync + cp.async — no tcgen05)
// ===========================================================================
__device__ __forceinline__ uint32_t smem_u32(const void* p) {
    uint32_t a;
    asm("{ .reg .u64 t; cvta.to.shared.u64 t, %1; cvt.u32.u64 %0, t; }"
        : "=r"(a) : "l"(p));
    return a;
}

__device__ __forceinline__ void ldmatrix_x4(uint32_t& r0, uint32_t& r1,
                                            uint32_t& r2, uint32_t& r3,
                                            uint32_t addr) {
    asm volatile("ldmatrix.sync.aligned.m8n8.x4.shared.b16 {%0,%1,%2,%3}, [%4];"
                 : "=r"(r0), "=r"(r1), "=r"(r2), "=r"(r3) : "r"(addr));
}

__device__ __forceinline__ void mma_16816(float* c, uint32_t a0, uint32_t a1,
                                          uint32_t a2, uint32_t a3,
                                          uint32_t b0, uint32_t b1) {
    asm volatile(
        "mma.sync.aligned.m16n8k16.row.col.f32.bf16.bf16.f32 "
        "{%0,%1,%2,%3}, {%4,%5,%6,%7}, {%8,%9}, {%0,%1,%2,%3};"
        : "+f"(c[0]), "+f"(c[1]), "+f"(c[2]), "+f"(c[3])
        : "r"(a0), "r"(a1), "r"(a2), "r"(a3), "r"(b0), "r"(b1));
}

__device__ __forceinline__ void cp16(uint32_t dst, const void* src) {
    asm volatile("cp.async.cg.shared.global [%0], [%1], 16;"
                 :: "r"(dst), "l"(src));
}
#define CP_COMMIT() asm volatile("cp.async.commit_group;" ::: "memory")
#define CP_WAIT1()  asm volatile("cp.async.wait_group 1;" ::: "memory")
#define CP_WAIT0()  asm volatile("cp.async.wait_group 0;" ::: "memory")

// ===========================================================================
// Scratch (no allocations allowed)
// ===========================================================================
__device__ float g_q[(size_t)BB * SS * HH * DH];     // 32 MB  [b,s,h,d]
__device__ float g_kv[(size_t)BB * SS * 2 * DH];     //  4 MB  [b,s, k|v]
__device__ float g_attn[(size_t)BB * SS * HH * DH];  // 32 MB  [b,s,h,d]
__device__ float g_rope[SS * DH];                    //  1 MB

__device__ __align__(256) __nv_bfloat16 g_xh[(size_t)BB * SS * DD];
__device__ __align__(256) __nv_bfloat16 g_xl[(size_t)BB * SS * DD];
__device__ __align__(256) __nv_bfloat16 g_qwh[(size_t)DD * DD];
__device__ __align__(256) __nv_bfloat16 g_qwl[(size_t)DD * DD];
__device__ __align__(256) __nv_bfloat16 g_kvwh[(size_t)2 * DH * DD];
__device__ __align__(256) __nv_bfloat16 g_kvwl[(size_t)2 * DH * DD];
__device__ __align__(256) __nv_bfloat16 g_owh[(size_t)DD * DD];
__device__ __align__(256) __nv_bfloat16 g_owl[(size_t)DD * DD];
__device__ __align__(256) __nv_bfloat16 g_ath[(size_t)BB * SS * DD];
__device__ __align__(256) __nv_bfloat16 g_atl[(size_t)BB * SS * DD];

// ===========================================================================
// fp32 -> (hi, lo) bf16 split.  v = hi + lo + O(2^-18 v)
// ===========================================================================
__global__ void split_bf16_kernel(const float* __restrict__ src,
                                  __nv_bfloat16* __restrict__ h,
                                  __nv_bfloat16* __restrict__ l, int n4)
{
    int i = blockIdx.x * blockDim.x + threadIdx.x;
    if (i >= n4) return;
    float4 v = *(const float4*)(src + (size_t)i * 4);
    __nv_bfloat16 h0 = __float2bfloat16(v.x);
    __nv_bfloat16 h1 = __float2bfloat16(v.y);
    __nv_bfloat16 h2 = __float2bfloat16(v.z);
    __nv_bfloat16 h3 = __float2bfloat16(v.w);
    __nv_bfloat16 l0 = __float2bfloat16(v.x - __bfloat162float(h0));
    __nv_bfloat16 l1 = __float2bfloat16(v.y - __bfloat162float(h1));
    __nv_bfloat16 l2 = __float2bfloat16(v.z - __bfloat162float(h2));
    __nv_bfloat16 l3 = __float2bfloat16(v.w - __bfloat162float(h3));
    __nv_bfloat162* hp = (__nv_bfloat162*)(h + (size_t)i * 4);
    __nv_bfloat162* lp = (__nv_bfloat162*)(l + (size_t)i * 4);
    hp[0] = __nv_bfloat162(h0, h1);
    hp[1] = __nv_bfloat162(h2, h3);
    lp[0] = __nv_bfloat162(l0, l1);
    lp[1] = __nv_bfloat162(l2, l3);
}

// ===========================================================================
// mma.sync split-bf16 GEMM: C[M,N] = A[M,K] @ W[N,K]^T + bias
//   3 passes (AhBh + AhBl + AlBh) accumulated in register fp32.
//   128x128 block tile, 8 warps (4x2), warp tile 32x64, BK=32,
//   cp.async double buffer. Padded smem rows: 40 bf16 (80B) -> ldmatrix
//   conflict-free. Requires M%128==0, N%128==0, K%32==0.
// ===========================================================================
#define GSTAGE 20480       // bytes per stage: A 128*80 + B 128*80
#define GROWB  80          // padded row bytes (40 bf16)

__device__ __forceinline__ void load_tiles(uint32_t sm_stage,
                                           const __nv_bfloat16* __restrict__ A,
                                           const __nv_bfloat16* __restrict__ B,
                                           int m0, int n0, int k0, int K, int tid)
{
#pragma unroll
    for (int t = 0; t < 4; t++) {
        int idx = tid + t * 256;          // 0..1023 16B chunks
        int isB = idx >> 9;
        int rem = idx & 511;
        int row = rem >> 2;               // 0..127
        int c16 = rem & 3;                // 16B col within 64B of data
        const __nv_bfloat16* src =
            (isB ? B + (size_t)(n0 + row) * K : A + (size_t)(m0 + row) * K)
            + k0 + c16 * 8;
        uint32_t dst = sm_stage + isB * 10240 + row * GROWB + c16 * 16;
        cp16(dst, src);
    }
}

__global__ void __launch_bounds__(256)
gemm_mma(const __nv_bfloat16* __restrict__ Ah, const __nv_bfloat16* __restrict__ Al,
         const __nv_bfloat16* __restrict__ Bh, const __nv_bfloat16* __restrict__ Bl,
         const float* __restrict__ bias, float* __restrict__ C,
         int M, int N, int K)
{
    __shared__ __align__(128) char smbuf[2 * GSTAGE];
    uint32_t smb = smem_u32(smbuf);

    int tid = threadIdx.x;
    int lid = tid & 31;
    int wid = tid >> 5;
    int wm = wid >> 1;          // 0..3 -> m offset wm*32
    int wn = wid & 1;           // 0..1 -> n offset wn*64
    int m0 = blockIdx.y * 128;
    int n0 = blockIdx.x * 128;

    const __nv_bfloat16* AP[3] = {Ah, Ah, Al};
    const __nv_bfloat16* BP[3] = {Bh, Bl, Bh};
    const int KCH = K >> 5;
    const int TOT = 3 * KCH;

    float acc[2][8][4];
#pragma unroll
    for (int s = 0; s < 2; s++)
#pragma unroll
        for (int nt = 0; nt < 8; nt++)
#pragma unroll
            for (int c = 0; c < 4; c++) acc[s][nt][c] = 0.f;

    load_tiles(smb, AP[0], BP[0], m0, n0, 0, K, tid);
    CP_COMMIT();

    for (int p = 0; p < TOT; p++) {
        if (p + 1 < TOT) {
            int pass = (p + 1) / KCH;
            int k0 = ((p + 1) % KCH) << 5;
            load_tiles(smb + (uint32_t)((p + 1) & 1) * GSTAGE,
                       AP[pass], BP[pass], m0, n0, k0, K, tid);
            CP_COMMIT();
            CP_WAIT1();
        } else {
            CP_WAIT0();
        }
        __syncthreads();

        uint32_t sb = smb + (uint32_t)(p & 1) * GSTAGE;
        uint32_t aW = sb + (uint32_t)(wm * 32) * GROWB;
        uint32_t bW = sb + 10240u + (uint32_t)(wn * 64) * GROWB;

#pragma unroll
        for (int ks = 0; ks < 2; ks++) {
            uint32_t af[2][4];
#pragma unroll
            for (int s = 0; s < 2; s++)
                ldmatrix_x4(af[s][0], af[s][1], af[s][2], af[s][3],
                            aW + (uint32_t)(s * 16 + (lid & 15)) * GROWB
                               + ks * 32 + ((lid >> 4) << 4));
            uint32_t bfm[4][4];
#pragma unroll
            for (int nb = 0; nb < 4; nb++)
                ldmatrix_x4(bfm[nb][0], bfm[nb][1], bfm[nb][2], bfm[nb][3],
                            bW + (uint32_t)(nb * 16 + (lid & 7) + ((lid >> 4) << 3)) * GROWB
                               + ks * 32 + (((lid >> 3) & 1) << 4));
#pragma unroll
            for (int s = 0; s < 2; s++)
#pragma unroll
                for (int nt = 0; nt < 8; nt++)
                    mma_16816(acc[s][nt],
                              af[s][0], af[s][1], af[s][2], af[s][3],
                              bfm[nt >> 1][(nt & 1) * 2],
                              bfm[nt >> 1][(nt & 1) * 2 + 1]);
        }
        __syncthreads();
    }

    // epilogue: bias + store fp32
#pragma unroll
    for (int s = 0; s < 2; s++) {
        int r0 = m0 + wm * 32 + s * 16 + (lid >> 2);
#pragma unroll
        for (int nt = 0; nt < 8; nt++) {
            int col = n0 + wn * 64 + nt * 8 + (lid & 3) * 2;
            float b0 = bias[col], b1 = bias[col + 1];
            float2 v0, v1;
            v0.x = acc[s][nt][0] + b0; v0.y = acc[s][nt][1] + b1;
            v1.x = acc[s][nt][2] + b0; v1.y = acc[s][nt][3] + b1;
            *(float2*)&C[(size_t)r0 * N + col] = v0;
            *(float2*)&C[(size_t)(r0 + 8) * N + col] = v1;
        }
    }
}

// ===========================================================================
// RoPE table + apply (double-precision trig: angles reach 2047 rad)
// ===========================================================================
__global__ void rope_table_kernel()
{
    int idx = blockIdx.x * blockDim.x + threadIdx.x;
    if (idx >= SS * 64) return;
    int s = idx >> 6;
    int p = idx & 63;
    double inv = pow(10000.0, -((double)(2 * p)) / 128.0);
    double ang = (double)s * inv;
    g_rope[s * DH + p]      = (float)cos(ang);
    g_rope[s * DH + p + 64] = (float)sin(ang);
}

__global__ void rope_apply_kernel(float* __restrict__ buf, int n_rows,
                                  int row_stride, int s_div)
{
    int idx = blockIdx.x * blockDim.x + threadIdx.x;
    if (idx >= n_rows * 64) return;
    int r = idx >> 6;
    int p = idx & 63;
    int s = (r / s_div) % SS;
    float c  = g_rope[s * DH + p];
    float sn = g_rope[s * DH + p + 64];
    float* row = buf + (size_t)r * row_stride;
    float a  = row[p];
    float b2 = row[p + 64];
    row[p]      = a * c - b2 * sn;
    row[p + 64] = b2 * c + a * sn;
}

// ===========================================================================
// Causal flash attention (MQA), fp32 — unchanged (passing, rel_err 3.3e-6).
// ===========================================================================
__global__ void __launch_bounds__(256)
attn_kernel(const float* __restrict__ Q, const float* __restrict__ KV,
            float* __restrict__ O)
{
    extern __shared__ float sm[];
    float* Qts = sm;                 // [d][r]  128*64
    float* Kts = Qts + 128 * 64;     // [d][r]  128*64
    float* Vs  = Kts + 128 * 64;     // [r][d]  64*128
    float* Ps  = Vs  + 64 * 128;     // [r][c]  64*64

    int qt  = blockIdx.x;
    int h   = blockIdx.y;
    int b   = blockIdx.z;
    int tid = threadIdx.x;
    int ty  = tid >> 4;
    int tx  = tid & 15;
    int q0  = qt * 64;
    const float scale = 0.08838834764831845f;

    size_t qbase = (((size_t)b * SS + q0) * HH + h) * DH;
#pragma unroll
    for (int t = 0; t < 8; t++) {
        int f  = tid + t * 256;
        int r  = f >> 5;
        int d4 = (f & 31) << 2;
        float4 v = *(const float4*)&Q[qbase + (size_t)r * (HH * DH) + d4];
        Qts[(d4 + 0) * 64 + r] = v.x;
        Qts[(d4 + 1) * 64 + r] = v.y;
        Qts[(d4 + 2) * 64 + r] = v.z;
        Qts[(d4 + 3) * 64 + r] = v.w;
    }

    float acc[4][8];
#pragma unroll
    for (int i = 0; i < 4; i++)
#pragma unroll
        for (int c = 0; c < 8; c++) acc[i][c] = 0.f;
    float run_max[4] = {-1e30f, -1e30f, -1e30f, -1e30f};
    float run_sum[4] = {0.f, 0.f, 0.f, 0.f};

    for (int kt = 0; kt <= qt; kt++) {
        int k0 = kt * 64;
        size_t kvbase = ((size_t)b * SS + k0) * (2 * DH);
#pragma unroll
        for (int t = 0; t < 8; t++) {
            int f  = tid + t * 256;
            int r  = f >> 5;
            int d4 = (f & 31) << 2;
            float4 kv4 = *(const float4*)&KV[kvbase + (size_t)r * (2 * DH) + d4];
            Kts[(d4 + 0) * 64 + r] = kv4.x;
            Kts[(d4 + 1) * 64 + r] = kv4.y;
            Kts[(d4 + 2) * 64 + r] = kv4.z;
            Kts[(d4 + 3) * 64 + r] = kv4.w;
            float4 vv = *(const float4*)&KV[kvbase + (size_t)r * (2 * DH) + DH + d4];
            *(float4*)&Vs[r * 128 + d4] = vv;
        }
        __syncthreads();

        float s_[4][4];
#pragma unroll
        for (int i = 0; i < 4; i++)
#pragma unroll
            for (int j = 0; j < 4; j++) s_[i][j] = 0.f;

#pragma unroll 4
        for (int d = 0; d < 128; d++) {
            float4 rq = *(const float4*)&Qts[d * 64 + ty * 4];
            float4 rk = *(const float4*)&Kts[d * 64 + tx * 4];
            float qa[4] = {rq.x, rq.y, rq.z, rq.w};
            float ka[4] = {rk.x, rk.y, rk.z, rk.w};
#pragma unroll
            for (int i = 0; i < 4; i++)
#pragma unroll
                for (int j = 0; j < 4; j++)
                    s_[i][j] += qa[i] * ka[j];
        }

#pragma unroll
        for (int i = 0; i < 4; i++) {
            int qg = q0 + ty * 4 + i;
            float m = -1e30f;
#pragma unroll
            for (int j = 0; j < 4; j++) {
                int kg = k0 + tx * 4 + j;
                float val = (kg <= qg) ? s_[i][j] * scale : -1e9f;
                s_[i][j] = val;
                m = fmaxf(m, val);
            }
#pragma unroll
            for (int off = 8; off > 0; off >>= 1)
                m = fmaxf(m, __shfl_xor_sync(0xffffffffu, m, off, 16));
            float mn = fmaxf(run_max[i], m);
            float f = __expf(run_max[i] - mn);
            run_max[i] = mn;
            float4 pr;
            pr.x = __expf(s_[i][0] - mn);
            pr.y = __expf(s_[i][1] - mn);
            pr.z = __expf(s_[i][2] - mn);
            pr.w = __expf(s_[i][3] - mn);
            float lsum = pr.x + pr.y + pr.z + pr.w;
#pragma unroll
            for (int off = 8; off > 0; off >>= 1)
                lsum += __shfl_xor_sync(0xffffffffu, lsum, off, 16);
            run_sum[i] = run_sum[i] * f + lsum;
#pragma unroll
            for (int c = 0; c < 8; c++) acc[i][c] *= f;
            *(float4*)&Ps[(ty * 4 + i) * 64 + tx * 4] = pr;
        }
        __syncthreads();

#pragma unroll 4
        for (int n = 0; n < 64; n++) {
            float4 rv0 = *(const float4*)&Vs[n * 128 + tx * 8];
            float4 rv1 = *(const float4*)&Vs[n * 128 + tx * 8 + 4];
#pragma unroll
            for (int i = 0; i < 4; i++) {
                float rp = Ps[(ty * 4 + i) * 64 + n];
                acc[i][0] += rp * rv0.x;
                acc[i][1] += rp * rv0.y;
                acc[i][2] += rp * rv0.z;
                acc[i][3] += rp * rv0.w;
                acc[i][4] += rp * rv1.x;
                acc[i][5] += rp * rv1.y;
                acc[i][6] += rp * rv1.z;
                acc[i][7] += rp * rv1.w;
            }
        }
        __syncthreads();
    }

#pragma unroll
    for (int i = 0; i < 4; i++) {
        float inv = 1.f / run_sum[i];
        int qg = q0 + ty * 4 + i;
        size_t obase = (((size_t)b * SS + qg) * HH + h) * DH + tx * 8;
        float4 v0, v1;
        v0.x = acc[i][0] * inv; v0.y = acc[i][1] * inv;
        v0.z = acc[i][2] * inv; v0.w = acc[i][3] * inv;
        v1.x = acc[i][4] * inv; v1.y = acc[i][5] * inv;
        v1.z = acc[i][6] * inv; v1.w = acc[i][7] * inv;
        *(float4*)&O[obase]     = v0;
        *(float4*)&O[obase + 4] = v1;
    }
}

// ===========================================================================
extern "C" void kernel_launch(void* const* d_in, const int* in_sizes, int n_in,
                              void* d_out, int out_size)
{
    const float* x   = (const float*)d_in[0];
    const float* qw  = (const float*)d_in[1];
    const float* qb  = (const float*)d_in[2];
    const float* kvw = (const float*)d_in[3];
    const float* kvb = (const float*)d_in[4];
    const float* ow  = (const float*)d_in[5];
    const float* ob  = (const float*)d_in[6];
    float* out = (float*)d_out;

    float *q_buf, *kv_buf, *attn_buf;
    cudaGetSymbolAddress((void**)&q_buf, g_q);
    cudaGetSymbolAddress((void**)&kv_buf, g_kv);
    cudaGetSymbolAddress((void**)&attn_buf, g_attn);
    __nv_bfloat16 *xh, *xl, *qwh, *qwl, *kvwh, *kvwl, *owh, *owl, *ath, *atl;
    cudaGetSymbolAddress((void**)&xh,   g_xh);
    cudaGetSymbolAddress((void**)&xl,   g_xl);
    cudaGetSymbolAddress((void**)&qwh,  g_qwh);
    cudaGetSymbolAddress((void**)&qwl,  g_qwl);
    cudaGetSymbolAddress((void**)&kvwh, g_kvwh);
    cudaGetSymbolAddress((void**)&kvwl, g_kvwl);
    cudaGetSymbolAddress((void**)&owh,  g_owh);
    cudaGetSymbolAddress((void**)&owl,  g_owl);
    cudaGetSymbolAddress((void**)&ath,  g_ath);
    cudaGetSymbolAddress((void**)&atl,  g_atl);

    const int M = BB * SS;   // 4096

    // 0) RoPE table
    rope_table_kernel<<<(SS * 64 + 255) / 256, 256>>>();

    // 1) bf16 splits of x and weights
    {
        int n4x = M * DD / 4;
        split_bf16_kernel<<<(n4x + 255) / 256, 256>>>(x, xh, xl, n4x);
        int n4q = DD * DD / 4;
        split_bf16_kernel<<<(n4q + 255) / 256, 256>>>(qw, qwh, qwl, n4q);
        int n4kv = 2 * DH * DD / 4;
        split_bf16_kernel<<<(n4kv + 255) / 256, 256>>>(kvw, kvwh, kvwl, n4kv);
        int n4o = DD * DD / 4;
        split_bf16_kernel<<<(n4o + 255) / 256, 256>>>(ow, owh, owl, n4o);
    }

    // 2) Q projection (tensor cores via mma.sync): [4096,2048]
    gemm_mma<<<dim3(DD / 128, M / 128), 256>>>(xh, xl, qwh, qwl, qb, q_buf, M, DD, DD);

    // 3) KV projection: [4096,256]
    gemm_mma<<<dim3(2, M / 128), 256>>>(xh, xl, kvwh, kvwl, kvb, kv_buf, M, 2 * DH, DD);

    // 4) RoPE on q and k
    {
        int nq = BB * SS * HH * 64;
        rope_apply_kernel<<<(nq + 255) / 256, 256>>>(q_buf, BB * SS * HH, DH, HH);
        int nk = BB * SS * 64;
        rope_apply_kernel<<<(nk + 255) / 256, 256>>>(kv_buf, BB * SS, 2 * DH, 1);
    }

    // 5) Causal MQA flash attention (fp32)
    {
        const int SMEM = (128 * 64 + 128 * 64 + 64 * 128 + 64 * 64) * sizeof(float);
        cudaFuncSetAttribute(attn_kernel, cudaFuncAttributeMaxDynamicSharedMemorySize, SMEM);
        attn_kernel<<<dim3(SS / 64, HH, BB), 256, SMEM>>>(q_buf, kv_buf, attn_buf);
    }

    // 6) Output projection (tensor cores via mma.sync)
    {
        int n4a = M * DD / 4;
        split_bf16_kernel<<<(n4a + 255) / 256, 256>>>(attn_buf, ath, atl, n4a);
        gemm_mma<<<dim3(DD / 128, M / 128), 256>>>(ath, atl, owh, owl, ob, out, M, DD, DD);
    }
}

// round 12
// speedup vs baseline: 2.6361x; 1.9807x over previous
#include <cuda_runtime.h>
#include <cuda_bf16.h>
#include <math.h>
#include <stdint.h>

#define BB 2
#define SS 2048
#define DD 2048
#define HH 16
#define DH 128

// ===========================================================================
// Helpers (base-ISA only: ldmatrix + mma.sync + cp.async — no tcgen05)
// ===========================================================================
__device__ __forceinline__ uint32_t smem_u32(const void* p) {
    uint32_t a;
    asm("{ .reg .u64 t; cvta.to.shared.u64 t, %1; cvt.u32.u64 %0, t; }"
        : "=r"(a) : "l"(p));
    return a;
}

__device__ __forceinline__ void ldmatrix_x4(uint32_t& r0, uint32_t& r1,
                                            uint32_t& r2, uint32_t& r3,
                                            uint32_t addr) {
    asm volatile("ldmatrix.sync.aligned.m8n8.x4.shared.b16 {%0,%1,%2,%3}, [%4];"
                 : "=r"(r0), "=r"(r1), "=r"(r2), "=r"(r3) : "r"(addr));
}

__device__ __forceinline__ void mma_16816(float* c, uint32_t a0, uint32_t a1,
                                          uint32_t a2, uint32_t a3,
                                          uint32_t b0, uint32_t b1) {
    asm volatile(
        "mma.sync.aligned.m16n8k16.row.col.f32.bf16.bf16.f32 "
        "{%0,%1,%2,%3}, {%4,%5,%6,%7}, {%8,%9}, {%0,%1,%2,%3};"
        : "+f"(c[0]), "+f"(c[1]), "+f"(c[2]), "+f"(c[3])
        : "r"(a0), "r"(a1), "r"(a2), "r"(a3), "r"(b0), "r"(b1));
}

__device__ __forceinline__ void cp16(uint32_t dst, const void* src) {
    asm volatile("cp.async.cg.shared.global [%0], [%1], 16;"
                 :: "r"(dst), "l"(src));
}
#define CP_COMMIT() asm volatile("cp.async.commit_group;" ::: "memory")
#define CP_WAIT1()  asm volatile("cp.async.wait_group 1;" ::: "memory")
#define CP_WAIT0()  asm volatile("cp.async.wait_group 0;" ::: "memory")

__device__ __forceinline__ uint32_t pack_bf(float lo, float hi) {
    __nv_bfloat162 v = __floats2bfloat162_rn(lo, hi);
    return *reinterpret_cast<uint32_t*>(&v);
}

// ===========================================================================
// Scratch (no allocations allowed)
// ===========================================================================
__device__ float g_q[(size_t)BB * SS * HH * DH];     // 32 MB  [b,s,h,d]
__device__ float g_kv[(size_t)BB * SS * 2 * DH];     //  4 MB  [b,s, k|v]
__device__ float g_rope[SS * DH];                    //  1 MB

__device__ __align__(256) __nv_bfloat16 g_xh[(size_t)BB * SS * DD];
__device__ __align__(256) __nv_bfloat16 g_xl[(size_t)BB * SS * DD];
__device__ __align__(256) __nv_bfloat16 g_qwh[(size_t)DD * DD];
__device__ __align__(256) __nv_bfloat16 g_qwl[(size_t)DD * DD];
__device__ __align__(256) __nv_bfloat16 g_kvwh[(size_t)2 * DH * DD];
__device__ __align__(256) __nv_bfloat16 g_kvwl[(size_t)2 * DH * DD];
__device__ __align__(256) __nv_bfloat16 g_owh[(size_t)DD * DD];
__device__ __align__(256) __nv_bfloat16 g_owl[(size_t)DD * DD];
__device__ __align__(256) __nv_bfloat16 g_ath[(size_t)BB * SS * DD];
__device__ __align__(256) __nv_bfloat16 g_atl[(size_t)BB * SS * DD];
// attention operand splits
__device__ __align__(256) __nv_bfloat16 g_qsh[(size_t)BB * SS * DD];
__device__ __align__(256) __nv_bfloat16 g_qsl[(size_t)BB * SS * DD];
__device__ __align__(256) __nv_bfloat16 g_ksh[(size_t)BB * SS * DH];
__device__ __align__(256) __nv_bfloat16 g_ksl[(size_t)BB * SS * DH];
__device__ __align__(256) __nv_bfloat16 g_vth[(size_t)BB * DH * SS];  // [b][d][s]
__device__ __align__(256) __nv_bfloat16 g_vtl[(size_t)BB * DH * SS];

// ===========================================================================
// fp32 -> (hi, lo) bf16 split.  v = hi + lo + O(2^-18 v)
// ===========================================================================
__global__ void split_bf16_kernel(const float* __restrict__ src,
                                  __nv_bfloat16* __restrict__ h,
                                  __nv_bfloat16* __restrict__ l, int n4)
{
    int i = blockIdx.x * blockDim.x + threadIdx.x;
    if (i >= n4) return;
    float4 v = *(const float4*)(src + (size_t)i * 4);
    __nv_bfloat16 h0 = __float2bfloat16(v.x);
    __nv_bfloat16 h1 = __float2bfloat16(v.y);
    __nv_bfloat16 h2 = __float2bfloat16(v.z);
    __nv_bfloat16 h3 = __float2bfloat16(v.w);
    __nv_bfloat16 l0 = __float2bfloat16(v.x - __bfloat162float(h0));
    __nv_bfloat16 l1 = __float2bfloat16(v.y - __bfloat162float(h1));
    __nv_bfloat16 l2 = __float2bfloat16(v.z - __bfloat162float(h2));
    __nv_bfloat16 l3 = __float2bfloat16(v.w - __bfloat162float(h3));
    __nv_bfloat162* hp = (__nv_bfloat162*)(h + (size_t)i * 4);
    __nv_bfloat162* lp = (__nv_bfloat162*)(l + (size_t)i * 4);
    hp[0] = __nv_bfloat162(h0, h1);
    hp[1] = __nv_bfloat162(h2, h3);
    lp[0] = __nv_bfloat162(l0, l1);
    lp[1] = __nv_bfloat162(l2, l3);
}

// K part of kv -> bf16 split, [b][s][128] contiguous
__global__ void ksplit_kernel(const float* __restrict__ kv,
                              __nv_bfloat16* __restrict__ kh,
                              __nv_bfloat16* __restrict__ kl)
{
    int i = blockIdx.x * blockDim.x + threadIdx.x;   // float4 over BB*SS*32
    if (i >= BB * SS * 32) return;
    int row = i >> 5, c = i & 31;
    float4 v = *(const float4*)(kv + (size_t)row * 256 + c * 4);
    size_t o = (size_t)row * 128 + c * 4;
    __nv_bfloat16 h0 = __float2bfloat16(v.x);
    __nv_bfloat16 h1 = __float2bfloat16(v.y);
    __nv_bfloat16 h2 = __float2bfloat16(v.z);
    __nv_bfloat16 h3 = __float2bfloat16(v.w);
    *(__nv_bfloat162*)&kh[o]     = __nv_bfloat162(h0, h1);
    *(__nv_bfloat162*)&kh[o + 2] = __nv_bfloat162(h2, h3);
    *(__nv_bfloat162*)&kl[o] = __nv_bfloat162(
        __float2bfloat16(v.x - __bfloat162float(h0)),
        __float2bfloat16(v.y - __bfloat162float(h1)));
    *(__nv_bfloat162*)&kl[o + 2] = __nv_bfloat162(
        __float2bfloat16(v.z - __bfloat162float(h2)),
        __float2bfloat16(v.w - __bfloat162float(h3)));
}

// V part of kv -> transposed bf16 split: vt[b][d][s]
__global__ void vtsplit_kernel(const float* __restrict__ kv,
                               __nv_bfloat16* __restrict__ vh,
                               __nv_bfloat16* __restrict__ vl)
{
    __shared__ float tile[32][33];
    int b = blockIdx.z, s0 = blockIdx.x * 32, d0 = blockIdx.y * 32;
#pragma unroll
    for (int j = 0; j < 4; j++) {
        int s = s0 + threadIdx.y + j * 8;
        tile[threadIdx.y + j * 8][threadIdx.x] =
            kv[((size_t)b * SS + s) * 256 + 128 + d0 + threadIdx.x];
    }
    __syncthreads();
#pragma unroll
    for (int j = 0; j < 4; j++) {
        int d = d0 + threadIdx.y + j * 8;
        int s = s0 + threadIdx.x;
        float v = tile[threadIdx.x][threadIdx.y + j * 8];
        __nv_bfloat16 hb = __float2bfloat16(v);
        size_t o = ((size_t)b * DH + d) * SS + s;
        vh[o] = hb;
        vl[o] = __float2bfloat16(v - __bfloat162float(hb));
    }
}

// ===========================================================================
// mma.sync split-bf16 GEMM (unchanged from R10): C = A @ W^T + bias
// ===========================================================================
#define GSTAGE 20480
#define GROWB  80

__device__ __forceinline__ void load_tiles(uint32_t sm_stage,
                                           const __nv_bfloat16* __restrict__ A,
                                           const __nv_bfloat16* __restrict__ B,
                                           int m0, int n0, int k0, int K, int tid)
{
#pragma unroll
    for (int t = 0; t < 4; t++) {
        int idx = tid + t * 256;
        int isB = idx >> 9;
        int rem = idx & 511;
        int row = rem >> 2;
        int c16 = rem & 3;
        const __nv_bfloat16* src =
            (isB ? B + (size_t)(n0 + row) * K : A + (size_t)(m0 + row) * K)
            + k0 + c16 * 8;
        uint32_t dst = sm_stage + isB * 10240 + row * GROWB + c16 * 16;
        cp16(dst, src);
    }
}

__global__ void __launch_bounds__(256)
gemm_mma(const __nv_bfloat16* __restrict__ Ah, const __nv_bfloat16* __restrict__ Al,
         const __nv_bfloat16* __restrict__ Bh, const __nv_bfloat16* __restrict__ Bl,
         const float* __restrict__ bias, float* __restrict__ C,
         int M, int N, int K)
{
    __shared__ __align__(128) char smbuf[2 * GSTAGE];
    uint32_t smb = smem_u32(smbuf);

    int tid = threadIdx.x;
    int lid = tid & 31;
    int wid = tid >> 5;
    int wm = wid >> 1;
    int wn = wid & 1;
    int m0 = blockIdx.y * 128;
    int n0 = blockIdx.x * 128;

    const __nv_bfloat16* AP[3] = {Ah, Ah, Al};
    const __nv_bfloat16* BP[3] = {Bh, Bl, Bh};
    const int KCH = K >> 5;
    const int TOT = 3 * KCH;

    float acc[2][8][4];
#pragma unroll
    for (int s = 0; s < 2; s++)
#pragma unroll
        for (int nt = 0; nt < 8; nt++)
#pragma unroll
            for (int c = 0; c < 4; c++) acc[s][nt][c] = 0.f;

    load_tiles(smb, AP[0], BP[0], m0, n0, 0, K, tid);
    CP_COMMIT();

    for (int p = 0; p < TOT; p++) {
        if (p + 1 < TOT) {
            int pass = (p + 1) / KCH;
            int k0 = ((p + 1) % KCH) << 5;
            load_tiles(smb + (uint32_t)((p + 1) & 1) * GSTAGE,
                       AP[pass], BP[pass], m0, n0, k0, K, tid);
            CP_COMMIT();
            CP_WAIT1();
        } else {
            CP_WAIT0();
        }
        __syncthreads();

        uint32_t sb = smb + (uint32_t)(p & 1) * GSTAGE;
        uint32_t aW = sb + (uint32_t)(wm * 32) * GROWB;
        uint32_t bW = sb + 10240u + (uint32_t)(wn * 64) * GROWB;

#pragma unroll
        for (int ks = 0; ks < 2; ks++) {
            uint32_t af[2][4];
#pragma unroll
            for (int s = 0; s < 2; s++)
                ldmatrix_x4(af[s][0], af[s][1], af[s][2], af[s][3],
                            aW + (uint32_t)(s * 16 + (lid & 15)) * GROWB
                               + ks * 32 + ((lid >> 4) << 4));
            uint32_t bfm[4][4];
#pragma unroll
            for (int nb = 0; nb < 4; nb++)
                ldmatrix_x4(bfm[nb][0], bfm[nb][1], bfm[nb][2], bfm[nb][3],
                            bW + (uint32_t)(nb * 16 + (lid & 7) + ((lid >> 4) << 3)) * GROWB
                               + ks * 32 + (((lid >> 3) & 1) << 4));
#pragma unroll
            for (int s = 0; s < 2; s++)
#pragma unroll
                for (int nt = 0; nt < 8; nt++)
                    mma_16816(acc[s][nt],
                              af[s][0], af[s][1], af[s][2], af[s][3],
                              bfm[nt >> 1][(nt & 1) * 2],
                              bfm[nt >> 1][(nt & 1) * 2 + 1]);
        }
        __syncthreads();
    }

#pragma unroll
    for (int s = 0; s < 2; s++) {
        int r0 = m0 + wm * 32 + s * 16 + (lid >> 2);
#pragma unroll
        for (int nt = 0; nt < 8; nt++) {
            int col = n0 + wn * 64 + nt * 8 + (lid & 3) * 2;
            float b0 = bias[col], b1 = bias[col + 1];
            float2 v0, v1;
            v0.x = acc[s][nt][0] + b0; v0.y = acc[s][nt][1] + b1;
            v1.x = acc[s][nt][2] + b0; v1.y = acc[s][nt][3] + b1;
            *(float2*)&C[(size_t)r0 * N + col] = v0;
            *(float2*)&C[(size_t)(r0 + 8) * N + col] = v1;
        }
    }
}

// ===========================================================================
// RoPE table + apply (double-precision trig: angles reach 2047 rad)
// ===========================================================================
__global__ void rope_table_kernel()
{
    int idx = blockIdx.x * blockDim.x + threadIdx.x;
    if (idx >= SS * 64) return;
    int s = idx >> 6;
    int p = idx & 63;
    double inv = pow(10000.0, -((double)(2 * p)) / 128.0);
    double ang = (double)s * inv;
    g_rope[s * DH + p]      = (float)cos(ang);
    g_rope[s * DH + p + 64] = (float)sin(ang);
}

__global__ void rope_apply_kernel(float* __restrict__ buf, int n_rows,
                                  int row_stride, int s_div)
{
    int idx = blockIdx.x * blockDim.x + threadIdx.x;
    if (idx >= n_rows * 64) return;
    int r = idx >> 6;
    int p = idx & 63;
    int s = (r / s_div) % SS;
    float c  = g_rope[s * DH + p];
    float sn = g_rope[s * DH + p + 64];
    float* row = buf + (size_t)r * row_stride;
    float a  = row[p];
    float b2 = row[p + 64];
    row[p]      = a * c - b2 * sn;
    row[p + 64] = b2 * c + a * sn;
}

// ===========================================================================
// Tensor-core causal MQA flash attention (split-bf16, mma.sync).
//   CTA: 128 q rows x (head, batch). 8 warps, 16 rows each. K tiles of 64.
//   QK^T = QhKh + QhKl + QlKh;  PV = PhVh + PhVl + PlVh (fp32 accum).
//   Smem panels: 32-k chunks, 80B row stride (R10-proven ldmatrix layout).
//   Output written directly as split bf16 (oh/ol) for the O-projection.
// ===========================================================================
#define Q_SM   0
#define QL_SM  40960
#define K_SM   81920
#define KL_SM  102400
#define V_SM   122880
#define VL_SM  143360
#define ATT_SMEM 163840

__global__ void __launch_bounds__(256)
attn_mma(const __nv_bfloat16* __restrict__ qsh, const __nv_bfloat16* __restrict__ qsl,
         const __nv_bfloat16* __restrict__ ksh, const __nv_bfloat16* __restrict__ ksl,
         const __nv_bfloat16* __restrict__ vth, const __nv_bfloat16* __restrict__ vtl,
         __nv_bfloat16* __restrict__ oh, __nv_bfloat16* __restrict__ ol)
{
    extern __shared__ char smem[];
    uint32_t smb = smem_u32(smem);
    int tid = threadIdx.x, lid = tid & 31, w = tid >> 5;
    int qt = gridDim.x - 1 - blockIdx.x;      // big tiles first
    int h = blockIdx.y, b = blockIdx.z;
    int q0 = qt * 128;
    int g = lid >> 2, t4 = lid & 3;
    const float scale = 0.08838834764831845f;  // 1/sqrt(128)

    // ---- Q tile load (both splits), 16 cp16/thread ----
#pragma unroll
    for (int t = 0; t < 16; t++) {
        int idx = tid + t * 256;            // 0..4095
        int sp  = idx >> 11;
        int rem = idx & 2047;
        int pan = rem >> 9;
        int r2  = rem & 511;
        int row = r2 >> 2;
        int c   = r2 & 3;
        const __nv_bfloat16* src = (sp ? qsl : qsh)
            + ((size_t)(b * SS + q0 + row) * HH + h) * DH + pan * 32 + c * 8;
        cp16(smb + (sp ? QL_SM : Q_SM) + pan * 10240 + row * 80 + c * 16, src);
    }
    CP_COMMIT();

    float oacc[16][4];
#pragma unroll
    for (int ob = 0; ob < 16; ob++)
#pragma unroll
        for (int c = 0; c < 4; c++) oacc[ob][c] = 0.f;
    float rm0 = -1e30f, rm1 = -1e30f, rs0 = 0.f, rs1 = 0.f;

    int qg0 = q0 + w * 16 + g;
    int qg1 = qg0 + 8;
    int ktmax = 2 * qt + 1;

    for (int kt = 0; kt <= ktmax; kt++) {
        int k0 = kt * 64;
        __syncthreads();                     // smem reuse barrier

        // ---- K tile (64 rows x 128k, both splits): 8 cp16/thread ----
#pragma unroll
        for (int tt = 0; tt < 8; tt++) {
            int idx = tid + tt * 256;        // 0..2047
            int sp  = idx >> 10;
            int rem = idx & 1023;
            int pan = rem >> 8;
            int r2  = rem & 255;
            int row = r2 >> 2;
            int c   = r2 & 3;
            const __nv_bfloat16* src = (sp ? ksl : ksh)
                + ((size_t)(b * SS) + k0 + row) * 128 + pan * 32 + c * 8;
            cp16(smb + (sp ? KL_SM : K_SM) + pan * 5120 + row * 80 + c * 16, src);
        }
        // ---- V^T tile (128 rows(dh) x 64k(seq), both splits): 8 cp16/thread ----
#pragma unroll
        for (int tt = 0; tt < 8; tt++) {
            int idx = tid + tt * 256;
            int sp  = idx >> 10;
            int rem = idx & 1023;
            int pan = rem >> 9;
            int r2  = rem & 511;
            int row = r2 >> 2;
            int c   = r2 & 3;
            const __nv_bfloat16* src = (sp ? vtl : vth)
                + ((size_t)(b * DH) + row) * SS + k0 + pan * 32 + c * 8;
            cp16(smb + (sp ? VL_SM : V_SM) + pan * 10240 + row * 80 + c * 16, src);
        }
        CP_COMMIT();
        CP_WAIT0();
        __syncthreads();

        if (k0 <= q0 + w * 16 + 15) {       // warp has unmasked rows
            // ---- S = Q K^T (3 split passes, fragment reuse) ----
            float sa[8][4];
#pragma unroll
            for (int i = 0; i < 8; i++)
#pragma unroll
                for (int c = 0; c < 4; c++) sa[i][c] = 0.f;

#pragma unroll
            for (int kp = 0; kp < 4; kp++) {
#pragma unroll
                for (int ks = 0; ks < 2; ks++) {
                    uint32_t aaddr = smb + kp * 10240
                        + (uint32_t)((w * 16 + (lid & 15)) * 80)
                        + ks * 32 + ((lid >> 4) << 4);
                    uint32_t qh[4], ql[4];
                    ldmatrix_x4(qh[0], qh[1], qh[2], qh[3], aaddr + Q_SM);
                    ldmatrix_x4(ql[0], ql[1], ql[2], ql[3], aaddr + QL_SM);
#pragma unroll
                    for (int nb = 0; nb < 4; nb++) {
                        uint32_t baddr = smb + kp * 5120
                            + (uint32_t)((nb * 16 + (lid & 7) + ((lid >> 4) << 3)) * 80)
                            + ks * 32 + (((lid >> 3) & 1) << 4);
                        uint32_t kh[4], kl[4];
                        ldmatrix_x4(kh[0], kh[1], kh[2], kh[3], baddr + K_SM);
                        ldmatrix_x4(kl[0], kl[1], kl[2], kl[3], baddr + KL_SM);
                        mma_16816(sa[2*nb],   qh[0],qh[1],qh[2],qh[3], kh[0],kh[1]);
                        mma_16816(sa[2*nb+1], qh[0],qh[1],qh[2],qh[3], kh[2],kh[3]);
                        mma_16816(sa[2*nb],   qh[0],qh[1],qh[2],qh[3], kl[0],kl[1]);
                        mma_16816(sa[2*nb+1], qh[0],qh[1],qh[2],qh[3], kl[2],kl[3]);
                        mma_16816(sa[2*nb],   ql[0],ql[1],ql[2],ql[3], kh[0],kh[1]);
                        mma_16816(sa[2*nb+1], ql[0],ql[1],ql[2],ql[3], kh[2],kh[3]);
                    }
                }
            }

            // ---- mask + scale + online softmax (registers + quad shfl) ----
            float m0 = -1e30f, m1 = -1e30f;
#pragma unroll
            for (int nt = 0; nt < 8; nt++) {
                int kg = k0 + nt * 8 + t4 * 2;
                sa[nt][0] = (kg     <= qg0) ? sa[nt][0] * scale : -1e9f;
                sa[nt][1] = (kg + 1 <= qg0) ? sa[nt][1] * scale : -1e9f;
                sa[nt][2] = (kg     <= qg1) ? sa[nt][2] * scale : -1e9f;
                sa[nt][3] = (kg + 1 <= qg1) ? sa[nt][3] * scale : -1e9f;
                m0 = fmaxf(m0, fmaxf(sa[nt][0], sa[nt][1]));
                m1 = fmaxf(m1, fmaxf(sa[nt][2], sa[nt][3]));
            }
            m0 = fmaxf(m0, __shfl_xor_sync(0xffffffffu, m0, 1));
            m0 = fmaxf(m0, __shfl_xor_sync(0xffffffffu, m0, 2));
            m1 = fmaxf(m1, __shfl_xor_sync(0xffffffffu, m1, 1));
            m1 = fmaxf(m1, __shfl_xor_sync(0xffffffffu, m1, 2));
            float mn0 = fmaxf(rm0, m0), mn1 = fmaxf(rm1, m1);
            float f0 = __expf(rm0 - mn0), f1 = __expf(rm1 - mn1);
            rm0 = mn0; rm1 = mn1;

            float s0 = 0.f, s1 = 0.f;
            uint32_t ph[4][4], pl[4][4];
#pragma unroll
            for (int nt = 0; nt < 8; nt++) {
                float p0 = __expf(sa[nt][0] - mn0);
                float p1 = __expf(sa[nt][1] - mn0);
                float p2 = __expf(sa[nt][2] - mn1);
                float p3 = __expf(sa[nt][3] - mn1);
                s0 += p0 + p1; s1 += p2 + p3;
                float h0 = __bfloat162float(__float2bfloat16(p0));
                float h1 = __bfloat162float(__float2bfloat16(p1));
                float h2 = __bfloat162float(__float2bfloat16(p2));
                float h3 = __bfloat162float(__float2bfloat16(p3));
                int j = nt >> 1, half = (nt & 1) * 2;
                ph[j][half]     = pack_bf(p0, p1);
                ph[j][half + 1] = pack_bf(p2, p3);
                pl[j][half]     = pack_bf(p0 - h0, p1 - h1);
                pl[j][half + 1] = pack_bf(p2 - h2, p3 - h3);
            }
            s0 += __shfl_xor_sync(0xffffffffu, s0, 1);
            s0 += __shfl_xor_sync(0xffffffffu, s0, 2);
            s1 += __shfl_xor_sync(0xffffffffu, s1, 1);
            s1 += __shfl_xor_sync(0xffffffffu, s1, 2);
            rs0 = rs0 * f0 + s0;
            rs1 = rs1 * f1 + s1;

#pragma unroll
            for (int ob = 0; ob < 16; ob++) {
                oacc[ob][0] *= f0; oacc[ob][1] *= f0;
                oacc[ob][2] *= f1; oacc[ob][3] *= f1;
            }

            // ---- O += P V (3 split passes, fragment reuse) ----
#pragma unroll
            for (int j = 0; j < 4; j++) {
                int kp = j >> 1, ks = j & 1;
#pragma unroll
                for (int nb = 0; nb < 8; nb++) {
                    uint32_t vaddr = smb + kp * 10240
                        + (uint32_t)((nb * 16 + (lid & 7) + ((lid >> 4) << 3)) * 80)
                        + ks * 32 + (((lid >> 3) & 1) << 4);
                    uint32_t vh[4], vl[4];
                    ldmatrix_x4(vh[0], vh[1], vh[2], vh[3], vaddr + V_SM);
                    ldmatrix_x4(vl[0], vl[1], vl[2], vl[3], vaddr + VL_SM);
                    mma_16816(oacc[2*nb],   ph[j][0],ph[j][1],ph[j][2],ph[j][3], vh[0],vh[1]);
                    mma_16816(oacc[2*nb+1], ph[j][0],ph[j][1],ph[j][2],ph[j][3], vh[2],vh[3]);
                    mma_16816(oacc[2*nb],   ph[j][0],ph[j][1],ph[j][2],ph[j][3], vl[0],vl[1]);
                    mma_16816(oacc[2*nb+1], ph[j][0],ph[j][1],ph[j][2],ph[j][3], vl[2],vl[3]);
                    mma_16816(oacc[2*nb],   pl[j][0],pl[j][1],pl[j][2],pl[j][3], vh[0],vh[1]);
                    mma_16816(oacc[2*nb+1], pl[j][0],pl[j][1],pl[j][2],pl[j][3], vh[2],vh[3]);
                }
            }
        }
    }

    // ---- epilogue: normalize, write split bf16 [b,s,h,d] ----
    float inv0 = 1.f / rs0, inv1 = 1.f / rs1;
#pragma unroll
    for (int ob = 0; ob < 16; ob++) {
        int col = ob * 8 + t4 * 2;
        size_t o0 = ((size_t)(b * SS + qg0) * HH + h) * DH + col;
        size_t o1 = ((size_t)(b * SS + qg1) * HH + h) * DH + col;
        float v0 = oacc[ob][0] * inv0, v1 = oacc[ob][1] * inv0;
        float v2 = oacc[ob][2] * inv1, v3 = oacc[ob][3] * inv1;
        __nv_bfloat162 h01 = __floats2bfloat162_rn(v0, v1);
        __nv_bfloat162 h23 = __floats2bfloat162_rn(v2, v3);
        *(__nv_bfloat162*)&oh[o0] = h01;
        *(__nv_bfloat162*)&oh[o1] = h23;
        *(__nv_bfloat162*)&ol[o0] = __floats2bfloat162_rn(
            v0 - __low2float(h01), v1 - __high2float(h01));
        *(__nv_bfloat162*)&ol[o1] = __floats2bfloat162_rn(
            v2 - __low2float(h23), v3 - __high2float(h23));
    }
}

// ===========================================================================
extern "C" void kernel_launch(void* const* d_in, const int* in_sizes, int n_in,
                              void* d_out, int out_size)
{
    const float* x   = (const float*)d_in[0];
    const float* qw  = (const float*)d_in[1];
    const float* qb  = (const float*)d_in[2];
    const float* kvw = (const float*)d_in[3];
    const float* kvb = (const float*)d_in[4];
    const float* ow  = (const float*)d_in[5];
    const float* ob  = (const float*)d_in[6];
    float* out = (float*)d_out;

    float *q_buf, *kv_buf;
    cudaGetSymbolAddress((void**)&q_buf, g_q);
    cudaGetSymbolAddress((void**)&kv_buf, g_kv);
    __nv_bfloat16 *xh, *xl, *qwh, *qwl, *kvwh, *kvwl, *owh, *owl, *ath, *atl;
    __nv_bfloat16 *qsh, *qsl, *ksh, *ksl, *vth, *vtl;
    cudaGetSymbolAddress((void**)&xh,   g_xh);
    cudaGetSymbolAddress((void**)&xl,   g_xl);
    cudaGetSymbolAddress((void**)&qwh,  g_qwh);
    cudaGetSymbolAddress((void**)&qwl,  g_qwl);
    cudaGetSymbolAddress((void**)&kvwh, g_kvwh);
    cudaGetSymbolAddress((void**)&kvwl, g_kvwl);
    cudaGetSymbolAddress((void**)&owh,  g_owh);
    cudaGetSymbolAddress((void**)&owl,  g_owl);
    cudaGetSymbolAddress((void**)&ath,  g_ath);
    cudaGetSymbolAddress((void**)&atl,  g_atl);
    cudaGetSymbolAddress((void**)&qsh,  g_qsh);
    cudaGetSymbolAddress((void**)&qsl,  g_qsl);
    cudaGetSymbolAddress((void**)&ksh,  g_ksh);
    cudaGetSymbolAddress((void**)&ksl,  g_ksl);
    cudaGetSymbolAddress((void**)&vth,  g_vth);
    cudaGetSymbolAddress((void**)&vtl,  g_vtl);

    const int M = BB * SS;   // 4096

    // 0) RoPE table
    rope_table_kernel<<<(SS * 64 + 255) / 256, 256>>>();

    // 1) bf16 splits of x and weights
    {
        int n4x = M * DD / 4;
        split_bf16_kernel<<<(n4x + 255) / 256, 256>>>(x, xh, xl, n4x);
        int n4q = DD * DD / 4;
        split_bf16_kernel<<<(n4q + 255) / 256, 256>>>(qw, qwh, qwl, n4q);
        int n4kv = 2 * DH * DD / 4;
        split_bf16_kernel<<<(n4kv + 255) / 256, 256>>>(kvw, kvwh, kvwl, n4kv);
        int n4o = DD * DD / 4;
        split_bf16_kernel<<<(n4o + 255) / 256, 256>>>(ow, owh, owl, n4o);
    }

    // 2) Projections (tensor cores)
    gemm_mma<<<dim3(DD / 128, M / 128), 256>>>(xh, xl, qwh, qwl, qb, q_buf, M, DD, DD);
    gemm_mma<<<dim3(2, M / 128), 256>>>(xh, xl, kvwh, kvwl, kvb, kv_buf, M, 2 * DH, DD);

    // 3) RoPE on q and k
    {
        int nq = BB * SS * HH * 64;
        rope_apply_kernel<<<(nq + 255) / 256, 256>>>(q_buf, BB * SS * HH, DH, HH);
        int nk = BB * SS * 64;
        rope_apply_kernel<<<(nk + 255) / 256, 256>>>(kv_buf, BB * SS, 2 * DH, 1);
    }

    // 4) Attention operand splits
    {
        int n4q = M * DD / 4;
        split_bf16_kernel<<<(n4q + 255) / 256, 256>>>(q_buf, qsh, qsl, n4q);
        int nk4 = BB * SS * 32;
        ksplit_kernel<<<(nk4 + 255) / 256, 256>>>(kv_buf, ksh, ksl);
        vtsplit_kernel<<<dim3(SS / 32, DH / 32, BB), dim3(32, 8)>>>(kv_buf, vth, vtl);
    }

    // 5) Tensor-core causal MQA flash attention -> split bf16 output
    {
        cudaFuncSetAttribute(attn_mma, cudaFuncAttributeMaxDynamicSharedMemorySize, ATT_SMEM);
        attn_mma<<<dim3(SS / 128, HH, BB), 256, ATT_SMEM>>>(qsh, qsl, ksh, ksl,
                                                            vth, vtl, ath, atl);
    }

    // 6) Output projection (tensor cores)
    gemm_mma<<<dim3(DD / 128, M / 128), 256>>>(ath, atl, owh, owl, ob, out, M, DD, DD);
}

// round 13
// speedup vs baseline: 2.8648x; 1.0868x over previous
#include <cuda_runtime.h>
#include <cuda_bf16.h>
#include <math.h>
#include <stdint.h>

#define BB 2
#define SS 2048
#define DD 2048
#define HH 16
#define DH 128

// ===========================================================================
// Helpers (base-ISA only: ldmatrix + mma.sync + cp.async — no tcgen05)
// ===========================================================================
__device__ __forceinline__ uint32_t smem_u32(const void* p) {
    uint32_t a;
    asm("{ .reg .u64 t; cvta.to.shared.u64 t, %1; cvt.u32.u64 %0, t; }"
        : "=r"(a) : "l"(p));
    return a;
}

__device__ __forceinline__ void ldmatrix_x4(uint32_t& r0, uint32_t& r1,
                                            uint32_t& r2, uint32_t& r3,
                                            uint32_t addr) {
    asm volatile("ldmatrix.sync.aligned.m8n8.x4.shared.b16 {%0,%1,%2,%3}, [%4];"
                 : "=r"(r0), "=r"(r1), "=r"(r2), "=r"(r3) : "r"(addr));
}

__device__ __forceinline__ void mma_16816(float* c, uint32_t a0, uint32_t a1,
                                          uint32_t a2, uint32_t a3,
                                          uint32_t b0, uint32_t b1) {
    asm volatile(
        "mma.sync.aligned.m16n8k16.row.col.f32.bf16.bf16.f32 "
        "{%0,%1,%2,%3}, {%4,%5,%6,%7}, {%8,%9}, {%0,%1,%2,%3};"
        : "+f"(c[0]), "+f"(c[1]), "+f"(c[2]), "+f"(c[3])
        : "r"(a0), "r"(a1), "r"(a2), "r"(a3), "r"(b0), "r"(b1));
}

__device__ __forceinline__ void cp16(uint32_t dst, const void* src) {
    asm volatile("cp.async.cg.shared.global [%0], [%1], 16;"
                 :: "r"(dst), "l"(src));
}
#define CP_COMMIT() asm volatile("cp.async.commit_group;" ::: "memory")
#define CP_WAIT1()  asm volatile("cp.async.wait_group 1;" ::: "memory")
#define CP_WAIT0()  asm volatile("cp.async.wait_group 0;" ::: "memory")

__device__ __forceinline__ uint32_t pack_bf(float lo, float hi) {
    __nv_bfloat162 v = __floats2bfloat162_rn(lo, hi);
    return *reinterpret_cast<uint32_t*>(&v);
}

// ===========================================================================
// Scratch (no allocations allowed)
// ===========================================================================
__device__ float g_q[(size_t)BB * SS * HH * DH];     // 32 MB  [b,s,h,d]
__device__ float g_kv[(size_t)BB * SS * 2 * DH];     //  4 MB  [b,s, k|v]
__device__ float g_rope[SS * DH];                    //  1 MB

__device__ __align__(256) __nv_bfloat16 g_xh[(size_t)BB * SS * DD];
__device__ __align__(256) __nv_bfloat16 g_xl[(size_t)BB * SS * DD];
__device__ __align__(256) __nv_bfloat16 g_qwh[(size_t)DD * DD];
__device__ __align__(256) __nv_bfloat16 g_qwl[(size_t)DD * DD];
__device__ __align__(256) __nv_bfloat16 g_kvwh[(size_t)2 * DH * DD];
__device__ __align__(256) __nv_bfloat16 g_kvwl[(size_t)2 * DH * DD];
__device__ __align__(256) __nv_bfloat16 g_owh[(size_t)DD * DD];
__device__ __align__(256) __nv_bfloat16 g_owl[(size_t)DD * DD];
__device__ __align__(256) __nv_bfloat16 g_ath[(size_t)BB * SS * DD];
__device__ __align__(256) __nv_bfloat16 g_atl[(size_t)BB * SS * DD];
// attention operand splits
__device__ __align__(256) __nv_bfloat16 g_qsh[(size_t)BB * SS * DD];
__device__ __align__(256) __nv_bfloat16 g_qsl[(size_t)BB * SS * DD];
__device__ __align__(256) __nv_bfloat16 g_ksh[(size_t)BB * SS * DH];
__device__ __align__(256) __nv_bfloat16 g_ksl[(size_t)BB * SS * DH];
__device__ __align__(256) __nv_bfloat16 g_vth[(size_t)BB * DH * SS];  // [b][d][s]
__device__ __align__(256) __nv_bfloat16 g_vtl[(size_t)BB * DH * SS];

// ===========================================================================
// fp32 -> (hi, lo) bf16 split.  v = hi + lo + O(2^-18 v)
// ===========================================================================
__global__ void split_bf16_kernel(const float* __restrict__ src,
                                  __nv_bfloat16* __restrict__ h,
                                  __nv_bfloat16* __restrict__ l, int n4)
{
    int i = blockIdx.x * blockDim.x + threadIdx.x;
    if (i >= n4) return;
    float4 v = *(const float4*)(src + (size_t)i * 4);
    __nv_bfloat16 h0 = __float2bfloat16(v.x);
    __nv_bfloat16 h1 = __float2bfloat16(v.y);
    __nv_bfloat16 h2 = __float2bfloat16(v.z);
    __nv_bfloat16 h3 = __float2bfloat16(v.w);
    __nv_bfloat16 l0 = __float2bfloat16(v.x - __bfloat162float(h0));
    __nv_bfloat16 l1 = __float2bfloat16(v.y - __bfloat162float(h1));
    __nv_bfloat16 l2 = __float2bfloat16(v.z - __bfloat162float(h2));
    __nv_bfloat16 l3 = __float2bfloat16(v.w - __bfloat162float(h3));
    __nv_bfloat162* hp = (__nv_bfloat162*)(h + (size_t)i * 4);
    __nv_bfloat162* lp = (__nv_bfloat162*)(l + (size_t)i * 4);
    hp[0] = __nv_bfloat162(h0, h1);
    hp[1] = __nv_bfloat162(h2, h3);
    lp[0] = __nv_bfloat162(l0, l1);
    lp[1] = __nv_bfloat162(l2, l3);
}

// K part of kv -> bf16 split, [b][s][128] contiguous
__global__ void ksplit_kernel(const float* __restrict__ kv,
                              __nv_bfloat16* __restrict__ kh,
                              __nv_bfloat16* __restrict__ kl)
{
    int i = blockIdx.x * blockDim.x + threadIdx.x;   // float4 over BB*SS*32
    if (i >= BB * SS * 32) return;
    int row = i >> 5, c = i & 31;
    float4 v = *(const float4*)(kv + (size_t)row * 256 + c * 4);
    size_t o = (size_t)row * 128 + c * 4;
    __nv_bfloat16 h0 = __float2bfloat16(v.x);
    __nv_bfloat16 h1 = __float2bfloat16(v.y);
    __nv_bfloat16 h2 = __float2bfloat16(v.z);
    __nv_bfloat16 h3 = __float2bfloat16(v.w);
    *(__nv_bfloat162*)&kh[o]     = __nv_bfloat162(h0, h1);
    *(__nv_bfloat162*)&kh[o + 2] = __nv_bfloat162(h2, h3);
    *(__nv_bfloat162*)&kl[o] = __nv_bfloat162(
        __float2bfloat16(v.x - __bfloat162float(h0)),
        __float2bfloat16(v.y - __bfloat162float(h1)));
    *(__nv_bfloat162*)&kl[o + 2] = __nv_bfloat162(
        __float2bfloat16(v.z - __bfloat162float(h2)),
        __float2bfloat16(v.w - __bfloat162float(h3)));
}

// V part of kv -> transposed bf16 split: vt[b][d][s]
__global__ void vtsplit_kernel(const float* __restrict__ kv,
                               __nv_bfloat16* __restrict__ vh,
                               __nv_bfloat16* __restrict__ vl)
{
    __shared__ float tile[32][33];
    int b = blockIdx.z, s0 = blockIdx.x * 32, d0 = blockIdx.y * 32;
#pragma unroll
    for (int j = 0; j < 4; j++) {
        int s = s0 + threadIdx.y + j * 8;
        tile[threadIdx.y + j * 8][threadIdx.x] =
            kv[((size_t)b * SS + s) * 256 + 128 + d0 + threadIdx.x];
    }
    __syncthreads();
#pragma unroll
    for (int j = 0; j < 4; j++) {
        int d = d0 + threadIdx.y + j * 8;
        int s = s0 + threadIdx.x;
        float v = tile[threadIdx.x][threadIdx.y + j * 8];
        __nv_bfloat16 hb = __float2bfloat16(v);
        size_t o = ((size_t)b * DH + d) * SS + s;
        vh[o] = hb;
        vl[o] = __float2bfloat16(v - __bfloat162float(hb));
    }
}

// ===========================================================================
// mma.sync split-bf16 GEMM v2: 128x256 block tile, 8 warps (2x4), warp 64x64.
//   3 passes (AhBh + AhBl + AlBh), fp32 register accum, cp.async double buffer.
//   Segmented N: cols [0,Nq) -> qC (stride Nq, bias qbias);
//                cols [Nq, Nq+256) -> kvC (stride 256, bias kvbias).
//   80B-padded smem rows (proven conflict-free ldmatrix layout).
// ===========================================================================
#define G2_STAGE 30720      // (128 + 256) rows * 80 B
#define GROWB 80

__global__ void __launch_bounds__(256)
gemm_mma2(const __nv_bfloat16* __restrict__ Ah, const __nv_bfloat16* __restrict__ Al,
          const __nv_bfloat16* __restrict__ qBh, const __nv_bfloat16* __restrict__ qBl,
          const __nv_bfloat16* __restrict__ kvBh, const __nv_bfloat16* __restrict__ kvBl,
          const float* __restrict__ qbias, const float* __restrict__ kvbias,
          float* __restrict__ qC, float* __restrict__ kvC,
          int M, int K, int Nq)
{
    extern __shared__ __align__(128) char smbuf[];
    uint32_t smb = smem_u32(smbuf);

    int tid = threadIdx.x;
    int lid = tid & 31;
    int wid = tid >> 5;
    int wm = wid >> 2;          // 0..1 -> m offset wm*64
    int wn = wid & 3;           // 0..3 -> n offset wn*64
    int m0 = blockIdx.y * 128;
    int n0f = blockIdx.x * 256;

    // segment select
    const __nv_bfloat16 *Bh, *Bl;
    const float* bias;
    float* C;
    int n0, Nc;
    if (n0f < Nq) {
        Bh = qBh + (size_t)n0f * K;  Bl = qBl + (size_t)n0f * K;
        bias = qbias; C = qC; n0 = n0f; Nc = Nq;
    } else {
        Bh = kvBh + (size_t)(n0f - Nq) * K;  Bl = kvBl + (size_t)(n0f - Nq) * K;
        bias = kvbias; C = kvC; n0 = n0f - Nq; Nc = 256;
    }
    const __nv_bfloat16* Ahp = Ah + (size_t)m0 * K;
    const __nv_bfloat16* Alp = Al + (size_t)m0 * K;

    const __nv_bfloat16* AP[3] = {Ahp, Ahp, Alp};
    const __nv_bfloat16* BP[3] = {Bh, Bl, Bh};
    const int KCH = K >> 5;
    const int TOT = 3 * KCH;

    float acc[4][8][4];
#pragma unroll
    for (int s = 0; s < 4; s++)
#pragma unroll
        for (int nt = 0; nt < 8; nt++)
#pragma unroll
            for (int c = 0; c < 4; c++) acc[s][nt][c] = 0.f;

    // prologue load (chunk 0)
    {
        const __nv_bfloat16* Ap = AP[0];
        const __nv_bfloat16* Bp = BP[0];
#pragma unroll
        for (int t = 0; t < 6; t++) {
            int idx = tid + t * 256;            // 0..1535 16B units
            int isB = (idx >= 512);
            int rem = isB ? idx - 512 : idx;
            int row = rem >> 2;
            int c16 = rem & 3;
            const __nv_bfloat16* src = (isB ? Bp : Ap) + (size_t)row * K + c16 * 8;
            cp16(smb + (isB ? 10240u : 0u) + row * GROWB + c16 * 16, src);
        }
        CP_COMMIT();
    }

    for (int p = 0; p < TOT; p++) {
        if (p + 1 < TOT) {
            int pass = (p + 1) / KCH;
            int k0 = ((p + 1) % KCH) << 5;
            const __nv_bfloat16* Ap = AP[pass];
            const __nv_bfloat16* Bp = BP[pass];
            uint32_t st = smb + (uint32_t)((p + 1) & 1) * G2_STAGE;
#pragma unroll
            for (int t = 0; t < 6; t++) {
                int idx = tid + t * 256;
                int isB = (idx >= 512);
                int rem = isB ? idx - 512 : idx;
                int row = rem >> 2;
                int c16 = rem & 3;
                const __nv_bfloat16* src = (isB ? Bp : Ap) + (size_t)row * K + k0 + c16 * 8;
                cp16(st + (isB ? 10240u : 0u) + row * GROWB + c16 * 16, src);
            }
            CP_COMMIT();
            CP_WAIT1();
        } else {
            CP_WAIT0();
        }
        __syncthreads();

        uint32_t sb = smb + (uint32_t)(p & 1) * G2_STAGE;
        uint32_t aW = sb + (uint32_t)(wm * 64) * GROWB;
        uint32_t bW = sb + 10240u + (uint32_t)(wn * 64) * GROWB;

#pragma unroll
        for (int ks = 0; ks < 2; ks++) {
            uint32_t af[4][4];
#pragma unroll
            for (int s = 0; s < 4; s++)
                ldmatrix_x4(af[s][0], af[s][1], af[s][2], af[s][3],
                            aW + (uint32_t)(s * 16 + (lid & 15)) * GROWB
                               + ks * 32 + ((lid >> 4) << 4));
            uint32_t bfm[4][4];
#pragma unroll
            for (int nb = 0; nb < 4; nb++)
                ldmatrix_x4(bfm[nb][0], bfm[nb][1], bfm[nb][2], bfm[nb][3],
                            bW + (uint32_t)(nb * 16 + (lid & 7) + ((lid >> 4) << 3)) * GROWB
                               + ks * 32 + (((lid >> 3) & 1) << 4));
#pragma unroll
            for (int s = 0; s < 4; s++)
#pragma unroll
                for (int nt = 0; nt < 8; nt++)
                    mma_16816(acc[s][nt],
                              af[s][0], af[s][1], af[s][2], af[s][3],
                              bfm[nt >> 1][(nt & 1) * 2],
                              bfm[nt >> 1][(nt & 1) * 2 + 1]);
        }
        __syncthreads();
    }

    // epilogue: bias + store fp32
#pragma unroll
    for (int s = 0; s < 4; s++) {
        int r0 = m0 + wm * 64 + s * 16 + (lid >> 2);
#pragma unroll
        for (int nt = 0; nt < 8; nt++) {
            int col = n0 + wn * 64 + nt * 8 + (lid & 3) * 2;
            float b0 = bias[col], b1 = bias[col + 1];
            float2 v0, v1;
            v0.x = acc[s][nt][0] + b0; v0.y = acc[s][nt][1] + b1;
            v1.x = acc[s][nt][2] + b0; v1.y = acc[s][nt][3] + b1;
            *(float2*)&C[(size_t)r0 * Nc + col] = v0;
            *(float2*)&C[(size_t)(r0 + 8) * Nc + col] = v1;
        }
    }
}

// ===========================================================================
// RoPE table + apply (double-precision trig: angles reach 2047 rad)
// ===========================================================================
__global__ void rope_table_kernel()
{
    int idx = blockIdx.x * blockDim.x + threadIdx.x;
    if (idx >= SS * 64) return;
    int s = idx >> 6;
    int p = idx & 63;
    double inv = pow(10000.0, -((double)(2 * p)) / 128.0);
    double ang = (double)s * inv;
    g_rope[s * DH + p]      = (float)cos(ang);
    g_rope[s * DH + p + 64] = (float)sin(ang);
}

__global__ void rope_apply_kernel(float* __restrict__ buf, int n_rows,
                                  int row_stride, int s_div)
{
    int idx = blockIdx.x * blockDim.x + threadIdx.x;
    if (idx >= n_rows * 64) return;
    int r = idx >> 6;
    int p = idx & 63;
    int s = (r / s_div) % SS;
    float c  = g_rope[s * DH + p];
    float sn = g_rope[s * DH + p + 64];
    float* row = buf + (size_t)r * row_stride;
    float a  = row[p];
    float b2 = row[p + 64];
    row[p]      = a * c - b2 * sn;
    row[p + 64] = b2 * c + a * sn;
}

// ===========================================================================
// Tensor-core causal MQA flash attention (split-bf16, mma.sync) — unchanged
// from the passing R12 version (1480 us, rel_err 3.4e-5).
// ===========================================================================
#define Q_SM   0
#define QL_SM  40960
#define K_SM   81920
#define KL_SM  102400
#define V_SM   122880
#define VL_SM  143360
#define ATT_SMEM 163840

__global__ void __launch_bounds__(256)
attn_mma(const __nv_bfloat16* __restrict__ qsh, const __nv_bfloat16* __restrict__ qsl,
         const __nv_bfloat16* __restrict__ ksh, const __nv_bfloat16* __restrict__ ksl,
         const __nv_bfloat16* __restrict__ vth, const __nv_bfloat16* __restrict__ vtl,
         __nv_bfloat16* __restrict__ oh, __nv_bfloat16* __restrict__ ol)
{
    extern __shared__ char smem[];
    uint32_t smb = smem_u32(smem);
    int tid = threadIdx.x, lid = tid & 31, w = tid >> 5;
    int qt = gridDim.x - 1 - blockIdx.x;      // big tiles first
    int h = blockIdx.y, b = blockIdx.z;
    int q0 = qt * 128;
    int g = lid >> 2, t4 = lid & 3;
    const float scale = 0.08838834764831845f;  // 1/sqrt(128)

    // ---- Q tile load (both splits), 16 cp16/thread ----
#pragma unroll
    for (int t = 0; t < 16; t++) {
        int idx = tid + t * 256;            // 0..4095
        int sp  = idx >> 11;
        int rem = idx & 2047;
        int pan = rem >> 9;
        int r2  = rem & 511;
        int row = r2 >> 2;
        int c   = r2 & 3;
        const __nv_bfloat16* src = (sp ? qsl : qsh)
            + ((size_t)(b * SS + q0 + row) * HH + h) * DH + pan * 32 + c * 8;
        cp16(smb + (sp ? QL_SM : Q_SM) + pan * 10240 + row * 80 + c * 16, src);
    }
    CP_COMMIT();

    float oacc[16][4];
#pragma unroll
    for (int ob = 0; ob < 16; ob++)
#pragma unroll
        for (int c = 0; c < 4; c++) oacc[ob][c] = 0.f;
    float rm0 = -1e30f, rm1 = -1e30f, rs0 = 0.f, rs1 = 0.f;

    int qg0 = q0 + w * 16 + g;
    int qg1 = qg0 + 8;
    int ktmax = 2 * qt + 1;

    for (int kt = 0; kt <= ktmax; kt++) {
        int k0 = kt * 64;
        __syncthreads();                     // smem reuse barrier

        // ---- K tile (64 rows x 128k, both splits): 8 cp16/thread ----
#pragma unroll
        for (int tt = 0; tt < 8; tt++) {
            int idx = tid + tt * 256;        // 0..2047
            int sp  = idx >> 10;
            int rem = idx & 1023;
            int pan = rem >> 8;
            int r2  = rem & 255;
            int row = r2 >> 2;
            int c   = r2 & 3;
            const __nv_bfloat16* src = (sp ? ksl : ksh)
                + ((size_t)(b * SS) + k0 + row) * 128 + pan * 32 + c * 8;
            cp16(smb + (sp ? KL_SM : K_SM) + pan * 5120 + row * 80 + c * 16, src);
        }
        // ---- V^T tile (128 rows(dh) x 64k(seq), both splits): 8 cp16/thread ----
#pragma unroll
        for (int tt = 0; tt < 8; tt++) {
            int idx = tid + tt * 256;
            int sp  = idx >> 10;
            int rem = idx & 1023;
            int pan = rem >> 9;
            int r2  = rem & 511;
            int row = r2 >> 2;
            int c   = r2 & 3;
            const __nv_bfloat16* src = (sp ? vtl : vth)
                + ((size_t)(b * DH) + row) * SS + k0 + pan * 32 + c * 8;
            cp16(smb + (sp ? VL_SM : V_SM) + pan * 10240 + row * 80 + c * 16, src);
        }
        CP_COMMIT();
        CP_WAIT0();
        __syncthreads();

        if (k0 <= q0 + w * 16 + 15) {       // warp has unmasked rows
            // ---- S = Q K^T (3 split passes, fragment reuse) ----
            float sa[8][4];
#pragma unroll
            for (int i = 0; i < 8; i++)
#pragma unroll
                for (int c = 0; c < 4; c++) sa[i][c] = 0.f;

#pragma unroll
            for (int kp = 0; kp < 4; kp++) {
#pragma unroll
                for (int ks = 0; ks < 2; ks++) {
                    uint32_t aaddr = smb + kp * 10240
                        + (uint32_t)((w * 16 + (lid & 15)) * 80)
                        + ks * 32 + ((lid >> 4) << 4);
                    uint32_t qh[4], ql[4];
                    ldmatrix_x4(qh[0], qh[1], qh[2], qh[3], aaddr + Q_SM);
                    ldmatrix_x4(ql[0], ql[1], ql[2], ql[3], aaddr + QL_SM);
#pragma unroll
                    for (int nb = 0; nb < 4; nb++) {
                        uint32_t baddr = smb + kp * 5120
                            + (uint32_t)((nb * 16 + (lid & 7) + ((lid >> 4) << 3)) * 80)
                            + ks * 32 + (((lid >> 3) & 1) << 4);
                        uint32_t kh[4], kl[4];
                        ldmatrix_x4(kh[0], kh[1], kh[2], kh[3], baddr + K_SM);
                        ldmatrix_x4(kl[0], kl[1], kl[2], kl[3], baddr + KL_SM);
                        mma_16816(sa[2*nb],   qh[0],qh[1],qh[2],qh[3], kh[0],kh[1]);
                        mma_16816(sa[2*nb+1], qh[0],qh[1],qh[2],qh[3], kh[2],kh[3]);
                        mma_16816(sa[2*nb],   qh[0],qh[1],qh[2],qh[3], kl[0],kl[1]);
                        mma_16816(sa[2*nb+1], qh[0],qh[1],qh[2],qh[3], kl[2],kl[3]);
                        mma_16816(sa[2*nb],   ql[0],ql[1],ql[2],ql[3], kh[0],kh[1]);
                        mma_16816(sa[2*nb+1], ql[0],ql[1],ql[2],ql[3], kh[2],kh[3]);
                    }
                }
            }

            // ---- mask + scale + online softmax (registers + quad shfl) ----
            float m0 = -1e30f, m1 = -1e30f;
#pragma unroll
            for (int nt = 0; nt < 8; nt++) {
                int kg = k0 + nt * 8 + t4 * 2;
                sa[nt][0] = (kg     <= qg0) ? sa[nt][0] * scale : -1e9f;
                sa[nt][1] = (kg + 1 <= qg0) ? sa[nt][1] * scale : -1e9f;
                sa[nt][2] = (kg     <= qg1) ? sa[nt][2] * scale : -1e9f;
                sa[nt][3] = (kg + 1 <= qg1) ? sa[nt][3] * scale : -1e9f;
                m0 = fmaxf(m0, fmaxf(sa[nt][0], sa[nt][1]));
                m1 = fmaxf(m1, fmaxf(sa[nt][2], sa[nt][3]));
            }
            m0 = fmaxf(m0, __shfl_xor_sync(0xffffffffu, m0, 1));
            m0 = fmaxf(m0, __shfl_xor_sync(0xffffffffu, m0, 2));
            m1 = fmaxf(m1, __shfl_xor_sync(0xffffffffu, m1, 1));
            m1 = fmaxf(m1, __shfl_xor_sync(0xffffffffu, m1, 2));
            float mn0 = fmaxf(rm0, m0), mn1 = fmaxf(rm1, m1);
            float f0 = __expf(rm0 - mn0), f1 = __expf(rm1 - mn1);
            rm0 = mn0; rm1 = mn1;

            float s0 = 0.f, s1 = 0.f;
            uint32_t ph[4][4], pl[4][4];
#pragma unroll
            for (int nt = 0; nt < 8; nt++) {
                float p0 = __expf(sa[nt][0] - mn0);
                float p1 = __expf(sa[nt][1] - mn0);
                float p2 = __expf(sa[nt][2] - mn1);
                float p3 = __expf(sa[nt][3] - mn1);
                s0 += p0 + p1; s1 += p2 + p3;
                float h0 = __bfloat162float(__float2bfloat16(p0));
                float h1 = __bfloat162float(__float2bfloat16(p1));
                float h2 = __bfloat162float(__float2bfloat16(p2));
                float h3 = __bfloat162float(__float2bfloat16(p3));
                int j = nt >> 1, half = (nt & 1) * 2;
                ph[j][half]     = pack_bf(p0, p1);
                ph[j][half + 1] = pack_bf(p2, p3);
                pl[j][half]     = pack_bf(p0 - h0, p1 - h1);
                pl[j][half + 1] = pack_bf(p2 - h2, p3 - h3);
            }
            s0 += __shfl_xor_sync(0xffffffffu, s0, 1);
            s0 += __shfl_xor_sync(0xffffffffu, s0, 2);
            s1 += __shfl_xor_sync(0xffffffffu, s1, 1);
            s1 += __shfl_xor_sync(0xffffffffu, s1, 2);
            rs0 = rs0 * f0 + s0;
            rs1 = rs1 * f1 + s1;

#pragma unroll
            for (int ob = 0; ob < 16; ob++) {
                oacc[ob][0] *= f0; oacc[ob][1] *= f0;
                oacc[ob][2] *= f1; oacc[ob][3] *= f1;
            }

            // ---- O += P V (3 split passes, fragment reuse) ----
#pragma unroll
            for (int j = 0; j < 4; j++) {
                int kp = j >> 1, ks = j & 1;
#pragma unroll
                for (int nb = 0; nb < 8; nb++) {
                    uint32_t vaddr = smb + kp * 10240
                        + (uint32_t)((nb * 16 + (lid & 7) + ((lid >> 4) << 3)) * 80)
                        + ks * 32 + (((lid >> 3) & 1) << 4);
                    uint32_t vh[4], vl[4];
                    ldmatrix_x4(vh[0], vh[1], vh[2], vh[3], vaddr + V_SM);
                    ldmatrix_x4(vl[0], vl[1], vl[2], vl[3], vaddr + VL_SM);
                    mma_16816(oacc[2*nb],   ph[j][0],ph[j][1],ph[j][2],ph[j][3], vh[0],vh[1]);
                    mma_16816(oacc[2*nb+1], ph[j][0],ph[j][1],ph[j][2],ph[j][3], vh[2],vh[3]);
                    mma_16816(oacc[2*nb],   ph[j][0],ph[j][1],ph[j][2],ph[j][3], vl[0],vl[1]);
                    mma_16816(oacc[2*nb+1], ph[j][0],ph[j][1],ph[j][2],ph[j][3], vl[2],vl[3]);
                    mma_16816(oacc[2*nb],   pl[j][0],pl[j][1],pl[j][2],pl[j][3], vh[0],vh[1]);
                    mma_16816(oacc[2*nb+1], pl[j][0],pl[j][1],pl[j][2],pl[j][3], vh[2],vh[3]);
                }
            }
        }
    }

    // ---- epilogue: normalize, write split bf16 [b,s,h,d] ----
    float inv0 = 1.f / rs0, inv1 = 1.f / rs1;
#pragma unroll
    for (int ob = 0; ob < 16; ob++) {
        int col = ob * 8 + t4 * 2;
        size_t o0 = ((size_t)(b * SS + qg0) * HH + h) * DH + col;
        size_t o1 = ((size_t)(b * SS + qg1) * HH + h) * DH + col;
        float v0 = oacc[ob][0] * inv0, v1 = oacc[ob][1] * inv0;
        float v2 = oacc[ob][2] * inv1, v3 = oacc[ob][3] * inv1;
        __nv_bfloat162 h01 = __floats2bfloat162_rn(v0, v1);
        __nv_bfloat162 h23 = __floats2bfloat162_rn(v2, v3);
        *(__nv_bfloat162*)&oh[o0] = h01;
        *(__nv_bfloat162*)&oh[o1] = h23;
        *(__nv_bfloat162*)&ol[o0] = __floats2bfloat162_rn(
            v0 - __low2float(h01), v1 - __high2float(h01));
        *(__nv_bfloat162*)&ol[o1] = __floats2bfloat162_rn(
            v2 - __low2float(h23), v3 - __high2float(h23));
    }
}

// ===========================================================================
extern "C" void kernel_launch(void* const* d_in, const int* in_sizes, int n_in,
                              void* d_out, int out_size)
{
    const float* x   = (const float*)d_in[0];
    const float* qw  = (const float*)d_in[1];
    const float* qb  = (const float*)d_in[2];
    const float* kvw = (const float*)d_in[3];
    const float* kvb = (const float*)d_in[4];
    const float* ow  = (const float*)d_in[5];
    const float* ob  = (const float*)d_in[6];
    float* out = (float*)d_out;

    float *q_buf, *kv_buf;
    cudaGetSymbolAddress((void**)&q_buf, g_q);
    cudaGetSymbolAddress((void**)&kv_buf, g_kv);
    __nv_bfloat16 *xh, *xl, *qwh, *qwl, *kvwh, *kvwl, *owh, *owl, *ath, *atl;
    __nv_bfloat16 *qsh, *qsl, *ksh, *ksl, *vth, *vtl;
    cudaGetSymbolAddress((void**)&xh,   g_xh);
    cudaGetSymbolAddress((void**)&xl,   g_xl);
    cudaGetSymbolAddress((void**)&qwh,  g_qwh);
    cudaGetSymbolAddress((void**)&qwl,  g_qwl);
    cudaGetSymbolAddress((void**)&kvwh, g_kvwh);
    cudaGetSymbolAddress((void**)&kvwl, g_kvwl);
    cudaGetSymbolAddress((void**)&owh,  g_owh);
    cudaGetSymbolAddress((void**)&owl,  g_owl);
    cudaGetSymbolAddress((void**)&ath,  g_ath);
    cudaGetSymbolAddress((void**)&atl,  g_atl);
    cudaGetSymbolAddress((void**)&qsh,  g_qsh);
    cudaGetSymbolAddress((void**)&qsl,  g_qsl);
    cudaGetSymbolAddress((void**)&ksh,  g_ksh);
    cudaGetSymbolAddress((void**)&ksl,  g_ksl);
    cudaGetSymbolAddress((void**)&vth,  g_vth);
    cudaGetSymbolAddress((void**)&vtl,  g_vtl);

    const int M = BB * SS;   // 4096
    const int G2_SMEM = 2 * G2_STAGE;  // 61440

    // 0) RoPE table
    rope_table_kernel<<<(SS * 64 + 255) / 256, 256>>>();

    // 1) bf16 splits of x and weights
    {
        int n4x = M * DD / 4;
        split_bf16_kernel<<<(n4x + 255) / 256, 256>>>(x, xh, xl, n4x);
        int n4q = DD * DD / 4;
        split_bf16_kernel<<<(n4q + 255) / 256, 256>>>(qw, qwh, qwl, n4q);
        int n4kv = 2 * DH * DD / 4;
        split_bf16_kernel<<<(n4kv + 255) / 256, 256>>>(kvw, kvwh, kvwl, n4kv);
        int n4o = DD * DD / 4;
        split_bf16_kernel<<<(n4o + 255) / 256, 256>>>(ow, owh, owl, n4o);
    }

    // 2) Fused Q+KV projection (tensor cores): N = 2048 + 256 = 2304
    cudaFuncSetAttribute(gemm_mma2, cudaFuncAttributeMaxDynamicSharedMemorySize, G2_SMEM);
    gemm_mma2<<<dim3((DD + 256) / 256, M / 128), 256, G2_SMEM>>>(
        xh, xl, qwh, qwl, kvwh, kvwl, qb, kvb, q_buf, kv_buf, M, DD, DD);

    // 3) RoPE on q and k
    {
        int nq = BB * SS * HH * 64;
        rope_apply_kernel<<<(nq + 255) / 256, 256>>>(q_buf, BB * SS * HH, DH, HH);
        int nk = BB * SS * 64;
        rope_apply_kernel<<<(nk + 255) / 256, 256>>>(kv_buf, BB * SS, 2 * DH, 1);
    }

    // 4) Attention operand splits
    {
        int n4q = M * DD / 4;
        split_bf16_kernel<<<(n4q + 255) / 256, 256>>>(q_buf, qsh, qsl, n4q);
        int nk4 = BB * SS * 32;
        ksplit_kernel<<<(nk4 + 255) / 256, 256>>>(kv_buf, ksh, ksl);
        vtsplit_kernel<<<dim3(SS / 32, DH / 32, BB), dim3(32, 8)>>>(kv_buf, vth, vtl);
    }

    // 5) Tensor-core causal MQA flash attention -> split bf16 output
    {
        cudaFuncSetAttribute(attn_mma, cudaFuncAttributeMaxDynamicSharedMemorySize, ATT_SMEM);
        attn_mma<<<dim3(SS / 128, HH, BB), 256, ATT_SMEM>>>(qsh, qsl, ksh, ksl,
                                                            vth, vtl, ath, atl);
    }

    // 6) Output projection (tensor cores): N = 2048 only (q-segment covers all)
    gemm_mma2<<<dim3(DD / 256, M / 128), 256, G2_SMEM>>>(
        ath, atl, owh, owl, owh, owl, ob, ob, out, out, M, DD, DD);
}

// round 15
// speedup vs baseline: 2.9587x; 1.0328x over previous
#include <cuda_runtime.h>
#include <cuda_bf16.h>
#include <math.h>
#include <stdint.h>

#define BB 2
#define SS 2048
#define DD 2048
#define HH 16
#define DH 128

// ===========================================================================
// Helpers (base-ISA only: ldmatrix + mma.sync + cp.async — no tcgen05)
// ===========================================================================
__device__ __forceinline__ uint32_t smem_u32(const void* p) {
    uint32_t a;
    asm("{ .reg .u64 t; cvta.to.shared.u64 t, %1; cvt.u32.u64 %0, t; }"
        : "=r"(a) : "l"(p));
    return a;
}

__device__ __forceinline__ void ldmatrix_x4(uint32_t& r0, uint32_t& r1,
                                            uint32_t& r2, uint32_t& r3,
                                            uint32_t addr) {
    asm volatile("ldmatrix.sync.aligned.m8n8.x4.shared.b16 {%0,%1,%2,%3}, [%4];"
                 : "=r"(r0), "=r"(r1), "=r"(r2), "=r"(r3) : "r"(addr));
}

__device__ __forceinline__ void mma_16816(float* c, uint32_t a0, uint32_t a1,
                                          uint32_t a2, uint32_t a3,
                                          uint32_t b0, uint32_t b1) {
    asm volatile(
        "mma.sync.aligned.m16n8k16.row.col.f32.bf16.bf16.f32 "
        "{%0,%1,%2,%3}, {%4,%5,%6,%7}, {%8,%9}, {%0,%1,%2,%3};"
        : "+f"(c[0]), "+f"(c[1]), "+f"(c[2]), "+f"(c[3])
        : "r"(a0), "r"(a1), "r"(a2), "r"(a3), "r"(b0), "r"(b1));
}

__device__ __forceinline__ void cp16(uint32_t dst, const void* src) {
    asm volatile("cp.async.cg.shared.global [%0], [%1], 16;"
                 :: "r"(dst), "l"(src));
}
#define CP_COMMIT() asm volatile("cp.async.commit_group;" ::: "memory")
#define CP_WAIT1()  asm volatile("cp.async.wait_group 1;" ::: "memory")
#define CP_WAIT0()  asm volatile("cp.async.wait_group 0;" ::: "memory")

__device__ __forceinline__ uint32_t pack_bf(float lo, float hi) {
    __nv_bfloat162 v = __floats2bfloat162_rn(lo, hi);
    return *reinterpret_cast<uint32_t*>(&v);
}

// split one float4 into hi/lo bf16x2 pairs and store
__device__ __forceinline__ void store_split4(__nv_bfloat16* h, __nv_bfloat16* l,
                                             size_t off, float4 v)
{
    __nv_bfloat162 h01 = __floats2bfloat162_rn(v.x, v.y);
    __nv_bfloat162 h23 = __floats2bfloat162_rn(v.z, v.w);
    *(__nv_bfloat162*)&h[off]     = h01;
    *(__nv_bfloat162*)&h[off + 2] = h23;
    *(__nv_bfloat162*)&l[off] = __floats2bfloat162_rn(
        v.x - __low2float(h01), v.y - __high2float(h01));
    *(__nv_bfloat162*)&l[off + 2] = __floats2bfloat162_rn(
        v.z - __low2float(h23), v.w - __high2float(h23));
}

// ===========================================================================
// Scratch (no allocations allowed)
// ===========================================================================
__device__ float g_q[(size_t)BB * SS * HH * DH];     // 32 MB  [b,s,h,d] (no rope)
__device__ float g_kv[(size_t)BB * SS * 2 * DH];     //  4 MB  [b,s, k|v] (no rope)
__device__ float g_rope[SS * DH];                    //  1 MB

__device__ __align__(256) __nv_bfloat16 g_xh[(size_t)BB * SS * DD];
__device__ __align__(256) __nv_bfloat16 g_xl[(size_t)BB * SS * DD];
__device__ __align__(256) __nv_bfloat16 g_qwh[(size_t)DD * DD];
__device__ __align__(256) __nv_bfloat16 g_qwl[(size_t)DD * DD];
__device__ __align__(256) __nv_bfloat16 g_kvwh[(size_t)2 * DH * DD];
__device__ __align__(256) __nv_bfloat16 g_kvwl[(size_t)2 * DH * DD];
__device__ __align__(256) __nv_bfloat16 g_owh[(size_t)DD * DD];
__device__ __align__(256) __nv_bfloat16 g_owl[(size_t)DD * DD];
__device__ __align__(256) __nv_bfloat16 g_ath[(size_t)BB * SS * DD];
__device__ __align__(256) __nv_bfloat16 g_atl[(size_t)BB * SS * DD];
// attention operand splits
__device__ __align__(256) __nv_bfloat16 g_qsh[(size_t)BB * SS * DD];
__device__ __align__(256) __nv_bfloat16 g_qsl[(size_t)BB * SS * DD];
__device__ __align__(256) __nv_bfloat16 g_ksh[(size_t)BB * SS * DH];
__device__ __align__(256) __nv_bfloat16 g_ksl[(size_t)BB * SS * DH];
__device__ __align__(256) __nv_bfloat16 g_vth[(size_t)BB * DH * SS];  // [b][d][s]
__device__ __align__(256) __nv_bfloat16 g_vtl[(size_t)BB * DH * SS];

// ===========================================================================
// fp32 -> (hi, lo) bf16 split, 4 float4/thread (MLP=4).
// Requires n4 == 4 * gridDim.x * blockDim.x.
// ===========================================================================
__global__ void split_bf16_kernel(const float* __restrict__ src,
                                  __nv_bfloat16* __restrict__ h,
                                  __nv_bfloat16* __restrict__ l, int n4)
{
    int S = gridDim.x * blockDim.x;
    int i = blockIdx.x * blockDim.x + threadIdx.x;
    float4 v[4];
#pragma unroll
    for (int j = 0; j < 4; j++)
        v[j] = *(const float4*)(src + (size_t)(i + j * S) * 4);
#pragma unroll
    for (int j = 0; j < 4; j++)
        store_split4(h, l, (size_t)(i + j * S) * 4, v[j]);
}

// ===========================================================================
// RoPE table via fp64 rotation recurrence: 2048 anchors, 64 steps each.
// ===========================================================================
__global__ void rope_table_kernel()
{
    int tid = blockIdx.x * blockDim.x + threadIdx.x;   // 0..2047
    if (tid >= 2048) return;
    int p  = tid & 63;
    int sb = tid >> 6;                                  // 32 s-blocks of 64
    double om = exp(-(2.0 * p / 128.0) * log(10000.0));
    double ang0 = (double)(sb * 64) * om;
    double c = cos(ang0), s = sin(ang0);
    double cw = cos(om), sw = sin(om);
#pragma unroll 4
    for (int i = 0; i < 64; i++) {
        int ss = sb * 64 + i;
        g_rope[ss * DH + p]      = (float)c;
        g_rope[ss * DH + p + 64] = (float)s;
        double c2 = c * cw - s * sw;
        s = s * cw + c * sw;
        c = c2;
    }
}

// ===========================================================================
// Fused rope + split for q: q_buf fp32 [b,s,h,128] -> qsh/qsl (rope'd).
// 1M threads, 4 pair-elements each.
// ===========================================================================
__global__ void rope_split_q_kernel(const float* __restrict__ q,
                                    __nv_bfloat16* __restrict__ h,
                                    __nv_bfloat16* __restrict__ l)
{
    int idx = blockIdx.x * blockDim.x + threadIdx.x;   // < BB*SS*HH*16
    int r  = idx >> 4;                                 // row 0..65535
    int c4 = (idx & 15) << 2;                          // p = c4..c4+3 (<64)
    int s  = (r >> 4) & (SS - 1);
    size_t base = (size_t)r * DH;
    float4 a  = *(const float4*)(q + base + c4);
    float4 b2 = *(const float4*)(q + base + 64 + c4);
    float4 cs = *(const float4*)(g_rope + (size_t)s * DH + c4);
    float4 sn = *(const float4*)(g_rope + (size_t)s * DH + 64 + c4);
    float4 ra, rb;
    ra.x = a.x * cs.x - b2.x * sn.x;  ra.y = a.y * cs.y - b2.y * sn.y;
    ra.z = a.z * cs.z - b2.z * sn.z;  ra.w = a.w * cs.w - b2.w * sn.w;
    rb.x = b2.x * cs.x + a.x * sn.x;  rb.y = b2.y * cs.y + a.y * sn.y;
    rb.z = b2.z * cs.z + a.z * sn.z;  rb.w = b2.w * cs.w + a.w * sn.w;
    store_split4(h, l, base + c4, ra);
    store_split4(h, l, base + 64 + c4, rb);
}

// Fused rope + split for k: kv rows 256-wide (K = first 128) -> ksh/ksl 128-wide.
__global__ void rope_ksplit_kernel(const float* __restrict__ kv,
                                   __nv_bfloat16* __restrict__ h,
                                   __nv_bfloat16* __restrict__ l)
{
    int idx = blockIdx.x * blockDim.x + threadIdx.x;   // < BB*SS*16
    int r  = idx >> 4;                                 // row 0..4095
    int c4 = (idx & 15) << 2;
    int s  = r & (SS - 1);
    size_t sbase = (size_t)r * 256;
    size_t obase = (size_t)r * DH;
    float4 a  = *(const float4*)(kv + sbase + c4);
    float4 b2 = *(const float4*)(kv + sbase + 64 + c4);
    float4 cs = *(const float4*)(g_rope + (size_t)s * DH + c4);
    float4 sn = *(const float4*)(g_rope + (size_t)s * DH + 64 + c4);
    float4 ra, rb;
    ra.x = a.x * cs.x - b2.x * sn.x;  ra.y = a.y * cs.y - b2.y * sn.y;
    ra.z = a.z * cs.z - b2.z * sn.z;  ra.w = a.w * cs.w - b2.w * sn.w;
    rb.x = b2.x * cs.x + a.x * sn.x;  rb.y = b2.y * cs.y + a.y * sn.y;
    rb.z = b2.z * cs.z + a.z * sn.z;  rb.w = b2.w * cs.w + a.w * sn.w;
    store_split4(h, l, obase + c4, ra);
    store_split4(h, l, obase + 64 + c4, rb);
}

// V part of kv -> transposed bf16 split: vt[b][d][s] (V never rope'd)
__global__ void vtsplit_kernel(const float* __restrict__ kv,
                               __nv_bfloat16* __restrict__ vh,
                               __nv_bfloat16* __restrict__ vl)
{
    __shared__ float tile[32][33];
    int b = blockIdx.z, s0 = blockIdx.x * 32, d0 = blockIdx.y * 32;
#pragma unroll
    for (int j = 0; j < 4; j++) {
        int s = s0 + threadIdx.y + j * 8;
        tile[threadIdx.y + j * 8][threadIdx.x] =
            kv[((size_t)b * SS + s) * 256 + 128 + d0 + threadIdx.x];
    }
    __syncthreads();
#pragma unroll
    for (int j = 0; j < 4; j++) {
        int d = d0 + threadIdx.y + j * 8;
        int s = s0 + threadIdx.x;
        float v = tile[threadIdx.x][threadIdx.y + j * 8];
        __nv_bfloat16 hb = __float2bfloat16(v);
        size_t o = ((size_t)b * DH + d) * SS + s;
        vh[o] = hb;
        vl[o] = __float2bfloat16(v - __bfloat162float(hb));
    }
}

// ===========================================================================
// mma.sync split-bf16 GEMM v2 (unchanged from R13, passing): 128x256 block
// tile, 8 warps (2x4), warp 64x64, segmented N (q | kv).
// ===========================================================================
#define G2_STAGE 30720
#define GROWB 80

__global__ void __launch_bounds__(256)
gemm_mma2(const __nv_bfloat16* __restrict__ Ah, const __nv_bfloat16* __restrict__ Al,
          const __nv_bfloat16* __restrict__ qBh, const __nv_bfloat16* __restrict__ qBl,
          const __nv_bfloat16* __restrict__ kvBh, const __nv_bfloat16* __restrict__ kvBl,
          const float* __restrict__ qbias, const float* __restrict__ kvbias,
          float* __restrict__ qC, float* __restrict__ kvC,
          int M, int K, int Nq)
{
    extern __shared__ __align__(128) char smbuf[];
    uint32_t smb = smem_u32(smbuf);

    int tid = threadIdx.x;
    int lid = tid & 31;
    int wid = tid >> 5;
    int wm = wid >> 2;
    int wn = wid & 3;
    int m0 = blockIdx.y * 128;
    int n0f = blockIdx.x * 256;

    const __nv_bfloat16 *Bh, *Bl;
    const float* bias;
    float* C;
    int n0, Nc;
    if (n0f < Nq) {
        Bh = qBh + (size_t)n0f * K;  Bl = qBl + (size_t)n0f * K;
        bias = qbias; C = qC; n0 = n0f; Nc = Nq;
    } else {
        Bh = kvBh + (size_t)(n0f - Nq) * K;  Bl = kvBl + (size_t)(n0f - Nq) * K;
        bias = kvbias; C = kvC; n0 = n0f - Nq; Nc = 256;
    }
    const __nv_bfloat16* Ahp = Ah + (size_t)m0 * K;
    const __nv_bfloat16* Alp = Al + (size_t)m0 * K;

    const __nv_bfloat16* AP[3] = {Ahp, Ahp, Alp};
    const __nv_bfloat16* BP[3] = {Bh, Bl, Bh};
    const int KCH = K >> 5;
    const int TOT = 3 * KCH;

    float acc[4][8][4];
#pragma unroll
    for (int s = 0; s < 4; s++)
#pragma unroll
        for (int nt = 0; nt < 8; nt++)
#pragma unroll
            for (int c = 0; c < 4; c++) acc[s][nt][c] = 0.f;

    {
        const __nv_bfloat16* Ap = AP[0];
        const __nv_bfloat16* Bp = BP[0];
#pragma unroll
        for (int t = 0; t < 6; t++) {
            int idx = tid + t * 256;
            int isB = (idx >= 512);
            int rem = isB ? idx - 512 : idx;
            int row = rem >> 2;
            int c16 = rem & 3;
            const __nv_bfloat16* src = (isB ? Bp : Ap) + (size_t)row * K + c16 * 8;
            cp16(smb + (isB ? 10240u : 0u) + row * GROWB + c16 * 16, src);
        }
        CP_COMMIT();
    }

    for (int p = 0; p < TOT; p++) {
        if (p + 1 < TOT) {
            int pass = (p + 1) / KCH;
            int k0 = ((p + 1) % KCH) << 5;
            const __nv_bfloat16* Ap = AP[pass];
            const __nv_bfloat16* Bp = BP[pass];
            uint32_t st = smb + (uint32_t)((p + 1) & 1) * G2_STAGE;
#pragma unroll
            for (int t = 0; t < 6; t++) {
                int idx = tid + t * 256;
                int isB = (idx >= 512);
                int rem = isB ? idx - 512 : idx;
                int row = rem >> 2;
                int c16 = rem & 3;
                const __nv_bfloat16* src = (isB ? Bp : Ap) + (size_t)row * K + k0 + c16 * 8;
                cp16(st + (isB ? 10240u : 0u) + row * GROWB + c16 * 16, src);
            }
            CP_COMMIT();
            CP_WAIT1();
        } else {
            CP_WAIT0();
        }
        __syncthreads();

        uint32_t sb = smb + (uint32_t)(p & 1) * G2_STAGE;
        uint32_t aW = sb + (uint32_t)(wm * 64) * GROWB;
        uint32_t bW = sb + 10240u + (uint32_t)(wn * 64) * GROWB;

#pragma unroll
        for (int ks = 0; ks < 2; ks++) {
            uint32_t af[4][4];
#pragma unroll
            for (int s = 0; s < 4; s++)
                ldmatrix_x4(af[s][0], af[s][1], af[s][2], af[s][3],
                            aW + (uint32_t)(s * 16 + (lid & 15)) * GROWB
                               + ks * 32 + ((lid >> 4) << 4));
            uint32_t bfm[4][4];
#pragma unroll
            for (int nb = 0; nb < 4; nb++)
                ldmatrix_x4(bfm[nb][0], bfm[nb][1], bfm[nb][2], bfm[nb][3],
                            bW + (uint32_t)(nb * 16 + (lid & 7) + ((lid >> 4) << 3)) * GROWB
                               + ks * 32 + (((lid >> 3) & 1) << 4));
#pragma unroll
            for (int s = 0; s < 4; s++)
#pragma unroll
                for (int nt = 0; nt < 8; nt++)
                    mma_16816(acc[s][nt],
                              af[s][0], af[s][1], af[s][2], af[s][3],
                              bfm[nt >> 1][(nt & 1) * 2],
                              bfm[nt >> 1][(nt & 1) * 2 + 1]);
        }
        __syncthreads();
    }

#pragma unroll
    for (int s = 0; s < 4; s++) {
        int r0 = m0 + wm * 64 + s * 16 + (lid >> 2);
#pragma unroll
        for (int nt = 0; nt < 8; nt++) {
            int col = n0 + wn * 64 + nt * 8 + (lid & 3) * 2;
            float b0 = bias[col], b1 = bias[col + 1];
            float2 v0, v1;
            v0.x = acc[s][nt][0] + b0; v0.y = acc[s][nt][1] + b1;
            v1.x = acc[s][nt][2] + b0; v1.y = acc[s][nt][3] + b1;
            *(float2*)&C[(size_t)r0 * Nc + col] = v0;
            *(float2*)&C[(size_t)(r0 + 8) * Nc + col] = v1;
        }
    }
}

// ===========================================================================
// Tensor-core causal MQA flash attention, v2:
//   Q fragments hoisted to registers (one-time extraction), K/V 2-stage
//   cp.async pipeline (80KB/stage), one __syncthreads per tile.
// Stage layout (base st): Kh@0 (4x5120), Kl@20480, Vh@40960 (2x10240), Vl@61440.
// ===========================================================================
#define ASTAGE 81920
#define ATT_SMEM (2 * ASTAGE)   // 163840

__global__ void __launch_bounds__(256)
attn_mma(const __nv_bfloat16* __restrict__ qsh, const __nv_bfloat16* __restrict__ qsl,
         const __nv_bfloat16* __restrict__ ksh, const __nv_bfloat16* __restrict__ ksl,
         const __nv_bfloat16* __restrict__ vth, const __nv_bfloat16* __restrict__ vtl,
         __nv_bfloat16* __restrict__ oh, __nv_bfloat16* __restrict__ ol)
{
    extern __shared__ char smem[];
    uint32_t smb = smem_u32(smem);
    int tid = threadIdx.x, lid = tid & 31, w = tid >> 5;
    int qt = gridDim.x - 1 - blockIdx.x;      // big tiles first
    int h = blockIdx.y, b = blockIdx.z;
    int q0 = qt * 128;
    int g = lid >> 2, t4 = lid & 3;
    const float scale = 0.08838834764831845f;  // 1/sqrt(128)

    // ---- one-time Q load into stage0 (Qh@0, Ql@40960), then extract frags ----
#pragma unroll
    for (int t = 0; t < 16; t++) {
        int idx = tid + t * 256;            // 0..4095
        int sp  = idx >> 11;
        int rem = idx & 2047;
        int pan = rem >> 9;
        int r2  = rem & 511;
        int row = r2 >> 2;
        int c   = r2 & 3;
        const __nv_bfloat16* src = (sp ? qsl : qsh)
            + ((size_t)(b * SS + q0 + row) * HH + h) * DH + pan * 32 + c * 8;
        cp16(smb + (sp ? 40960u : 0u) + pan * 10240 + row * 80 + c * 16, src);
    }
    CP_COMMIT();
    CP_WAIT0();
    __syncthreads();

    uint32_t qf[4][2][2][4];     // [kp][ks][split][reg]
#pragma unroll
    for (int kp = 0; kp < 4; kp++)
#pragma unroll
        for (int ks = 0; ks < 2; ks++) {
            uint32_t aaddr = smb + kp * 10240
                + (uint32_t)((w * 16 + (lid & 15)) * 80)
                + ks * 32 + ((lid >> 4) << 4);
            ldmatrix_x4(qf[kp][ks][0][0], qf[kp][ks][0][1],
                        qf[kp][ks][0][2], qf[kp][ks][0][3], aaddr);
            ldmatrix_x4(qf[kp][ks][1][0], qf[kp][ks][1][1],
                        qf[kp][ks][1][2], qf[kp][ks][1][3], aaddr + 40960u);
        }
    __syncthreads();             // all warps done reading Q before K/V overwrite

    float oacc[16][4];
#pragma unroll
    for (int ob = 0; ob < 16; ob++)
#pragma unroll
        for (int c = 0; c < 4; c++) oacc[ob][c] = 0.f;
    float rm0 = -1e30f, rm1 = -1e30f, rs0 = 0.f, rs1 = 0.f;

    int qg0 = q0 + w * 16 + g;
    int qg1 = qg0 + 8;
    int ktmax = 2 * qt + 1;

    // K/V tile loader into stage base st
    auto load_kv = [&](int kt, uint32_t st) {
        int k0 = kt * 64;
#pragma unroll
        for (int tt = 0; tt < 8; tt++) {       // K: both splits
            int idx = tid + tt * 256;
            int sp  = idx >> 10;
            int rem = idx & 1023;
            int pan = rem >> 8;
            int r2  = rem & 255;
            int row = r2 >> 2;
            int c   = r2 & 3;
            const __nv_bfloat16* src = (sp ? ksl : ksh)
                + ((size_t)(b * SS) + k0 + row) * 128 + pan * 32 + c * 8;
            cp16(st + sp * 20480u + pan * 5120 + row * 80 + c * 16, src);
        }
#pragma unroll
        for (int tt = 0; tt < 8; tt++) {       // V^T: both splits
            int idx = tid + tt * 256;
            int sp  = idx >> 10;
            int rem = idx & 1023;
            int pan = rem >> 9;
            int r2  = rem & 511;
            int row = r2 >> 2;
            int c   = r2 & 3;
            const __nv_bfloat16* src = (sp ? vtl : vth)
                + ((size_t)(b * DH) + row) * SS + k0 + pan * 32 + c * 8;
            cp16(st + 40960u + sp * 20480u + pan * 10240 + row * 80 + c * 16, src);
        }
        CP_COMMIT();
    };

    load_kv(0, smb);             // prefetch kt=0 into stage0

    for (int kt = 0; kt <= ktmax; kt++) {
        int k0 = kt * 64;
        CP_WAIT0();
        __syncthreads();          // stage kt ready; all warps done with other stage
        if (kt + 1 <= ktmax)
            load_kv(kt + 1, smb + (uint32_t)((kt + 1) & 1) * ASTAGE);

        uint32_t st = smb + (uint32_t)(kt & 1) * ASTAGE;

        if (k0 <= q0 + w * 16 + 15) {       // warp has unmasked rows
            // ---- S = Q K^T (3 split passes, Q from registers) ----
            float sa[8][4];
#pragma unroll
            for (int i = 0; i < 8; i++)
#pragma unroll
                for (int c = 0; c < 4; c++) sa[i][c] = 0.f;

#pragma unroll
            for (int kp = 0; kp < 4; kp++) {
#pragma unroll
                for (int ks = 0; ks < 2; ks++) {
                    const uint32_t* qh = qf[kp][ks][0];
                    const uint32_t* ql = qf[kp][ks][1];
#pragma unroll
                    for (int nb = 0; nb < 4; nb++) {
                        uint32_t baddr = st + kp * 5120
                            + (uint32_t)((nb * 16 + (lid & 7) + ((lid >> 4) << 3)) * 80)
                            + ks * 32 + (((lid >> 3) & 1) << 4);
                        uint32_t kh[4], kl[4];
                        ldmatrix_x4(kh[0], kh[1], kh[2], kh[3], baddr);
                        ldmatrix_x4(kl[0], kl[1], kl[2], kl[3], baddr + 20480u);
                        mma_16816(sa[2*nb],   qh[0],qh[1],qh[2],qh[3], kh[0],kh[1]);
                        mma_16816(sa[2*nb+1], qh[0],qh[1],qh[2],qh[3], kh[2],kh[3]);
                        mma_16816(sa[2*nb],   qh[0],qh[1],qh[2],qh[3], kl[0],kl[1]);
                        mma_16816(sa[2*nb+1], qh[0],qh[1],qh[2],qh[3], kl[2],kl[3]);
                        mma_16816(sa[2*nb],   ql[0],ql[1],ql[2],ql[3], kh[0],kh[1]);
                        mma_16816(sa[2*nb+1], ql[0],ql[1],ql[2],ql[3], kh[2],kh[3]);
                    }
                }
            }

            // ---- mask + scale + online softmax (registers + quad shfl) ----
            float m0 = -1e30f, m1 = -1e30f;
#pragma unroll
            for (int nt = 0; nt < 8; nt++) {
                int kg = k0 + nt * 8 + t4 * 2;
                sa[nt][0] = (kg     <= qg0) ? sa[nt][0] * scale : -1e9f;
                sa[nt][1] = (kg + 1 <= qg0) ? sa[nt][1] * scale : -1e9f;
                sa[nt][2] = (kg     <= qg1) ? sa[nt][2] * scale : -1e9f;
                sa[nt][3] = (kg + 1 <= qg1) ? sa[nt][3] * scale : -1e9f;
                m0 = fmaxf(m0, fmaxf(sa[nt][0], sa[nt][1]));
                m1 = fmaxf(m1, fmaxf(sa[nt][2], sa[nt][3]));
            }
            m0 = fmaxf(m0, __shfl_xor_sync(0xffffffffu, m0, 1));
            m0 = fmaxf(m0, __shfl_xor_sync(0xffffffffu, m0, 2));
            m1 = fmaxf(m1, __shfl_xor_sync(0xffffffffu, m1, 1));
            m1 = fmaxf(m1, __shfl_xor_sync(0xffffffffu, m1, 2));
            float mn0 = fmaxf(rm0, m0), mn1 = fmaxf(rm1, m1);
            float f0 = __expf(rm0 - mn0), f1 = __expf(rm1 - mn1);
            rm0 = mn0; rm1 = mn1;

            float s0 = 0.f, s1 = 0.f;
            uint32_t ph[4][4], pl[4][4];
#pragma unroll
            for (int nt = 0; nt < 8; nt++) {
                float p0 = __expf(sa[nt][0] - mn0);
                float p1 = __expf(sa[nt][1] - mn0);
                float p2 = __expf(sa[nt][2] - mn1);
                float p3 = __expf(sa[nt][3] - mn1);
                s0 += p0 + p1; s1 += p2 + p3;
                float h0 = __bfloat162float(__float2bfloat16(p0));
                float h1 = __bfloat162float(__float2bfloat16(p1));
                float h2 = __bfloat162float(__float2bfloat16(p2));
                float h3 = __bfloat162float(__float2bfloat16(p3));
                int j = nt >> 1, half = (nt & 1) * 2;
                ph[j][half]     = pack_bf(p0, p1);
                ph[j][half + 1] = pack_bf(p2, p3);
                pl[j][half]     = pack_bf(p0 - h0, p1 - h1);
                pl[j][half + 1] = pack_bf(p2 - h2, p3 - h3);
            }
            s0 += __shfl_xor_sync(0xffffffffu, s0, 1);
            s0 += __shfl_xor_sync(0xffffffffu, s0, 2);
            s1 += __shfl_xor_sync(0xffffffffu, s1, 1);
            s1 += __shfl_xor_sync(0xffffffffu, s1, 2);
            rs0 = rs0 * f0 + s0;
            rs1 = rs1 * f1 + s1;

#pragma unroll
            for (int ob = 0; ob < 16; ob++) {
                oacc[ob][0] *= f0; oacc[ob][1] *= f0;
                oacc[ob][2] *= f1; oacc[ob][3] *= f1;
            }

            // ---- O += P V (3 split passes) ----
#pragma unroll
            for (int j = 0; j < 4; j++) {
                int kp = j >> 1, ks = j & 1;
#pragma unroll
                for (int nb = 0; nb < 8; nb++) {
                    uint32_t vaddr = st + 40960u + kp * 10240
                        + (uint32_t)((nb * 16 + (lid & 7) + ((lid >> 4) << 3)) * 80)
                        + ks * 32 + (((lid >> 3) & 1) << 4);
                    uint32_t vh[4], vl[4];
                    ldmatrix_x4(vh[0], vh[1], vh[2], vh[3], vaddr);
                    ldmatrix_x4(vl[0], vl[1], vl[2], vl[3], vaddr + 20480u);
                    mma_16816(oacc[2*nb],   ph[j][0],ph[j][1],ph[j][2],ph[j][3], vh[0],vh[1]);
                    mma_16816(oacc[2*nb+1], ph[j][0],ph[j][1],ph[j][2],ph[j][3], vh[2],vh[3]);
                    mma_16816(oacc[2*nb],   ph[j][0],ph[j][1],ph[j][2],ph[j][3], vl[0],vl[1]);
                    mma_16816(oacc[2*nb+1], ph[j][0],ph[j][1],ph[j][2],ph[j][3], vl[2],vl[3]);
                    mma_16816(oacc[2*nb],   pl[j][0],pl[j][1],pl[j][2],pl[j][3], vh[0],vh[1]);
                    mma_16816(oacc[2*nb+1], pl[j][0],pl[j][1],pl[j][2],pl[j][3], vh[2],vh[3]);
                }
            }
        }
    }

    // ---- epilogue: normalize, write split bf16 [b,s,h,d] ----
    float inv0 = 1.f / rs0, inv1 = 1.f / rs1;
#pragma unroll
    for (int ob = 0; ob < 16; ob++) {
        int col = ob * 8 + t4 * 2;
        size_t o0 = ((size_t)(b * SS + qg0) * HH + h) * DH + col;
        size_t o1 = ((size_t)(b * SS + qg1) * HH + h) * DH + col;
        float v0 = oacc[ob][0] * inv0, v1 = oacc[ob][1] * inv0;
        float v2 = oacc[ob][2] * inv1, v3 = oacc[ob][3] * inv1;
        __nv_bfloat162 h01 = __floats2bfloat162_rn(v0, v1);
        __nv_bfloat162 h23 = __floats2bfloat162_rn(v2, v3);
        *(__nv_bfloat162*)&oh[o0] = h01;
        *(__nv_bfloat162*)&oh[o1] = h23;
        *(__nv_bfloat162*)&ol[o0] = __floats2bfloat162_rn(
            v0 - __low2float(h01), v1 - __high2float(h01));
        *(__nv_bfloat162*)&ol[o1] = __floats2bfloat162_rn(
            v2 - __low2float(h23), v3 - __high2float(h23));
    }
}

// ===========================================================================
extern "C" void kernel_launch(void* const* d_in, const int* in_sizes, int n_in,
                              void* d_out, int out_size)
{
    const float* x   = (const float*)d_in[0];
    const float* qw  = (const float*)d_in[1];
    const float* qb  = (const float*)d_in[2];
    const float* kvw = (const float*)d_in[3];
    const float* kvb = (const float*)d_in[4];
    const float* ow  = (const float*)d_in[5];
    const float* ob  = (const float*)d_in[6];
    float* out = (float*)d_out;

    float *q_buf, *kv_buf;
    cudaGetSymbolAddress((void**)&q_buf, g_q);
    cudaGetSymbolAddress((void**)&kv_buf, g_kv);
    __nv_bfloat16 *xh, *xl, *qwh, *qwl, *kvwh, *kvwl, *owh, *owl, *ath, *atl;
    __nv_bfloat16 *qsh, *qsl, *ksh, *ksl, *vth, *vtl;
    cudaGetSymbolAddress((void**)&xh,   g_xh);
    cudaGetSymbolAddress((void**)&xl,   g_xl);
    cudaGetSymbolAddress((void**)&qwh,  g_qwh);
    cudaGetSymbolAddress((void**)&qwl,  g_qwl);
    cudaGetSymbolAddress((void**)&kvwh, g_kvwh);
    cudaGetSymbolAddress((void**)&kvwl, g_kvwl);
    cudaGetSymbolAddress((void**)&owh,  g_owh);
    cudaGetSymbolAddress((void**)&owl,  g_owl);
    cudaGetSymbolAddress((void**)&ath,  g_ath);
    cudaGetSymbolAddress((void**)&atl,  g_atl);
    cudaGetSymbolAddress((void**)&qsh,  g_qsh);
    cudaGetSymbolAddress((void**)&qsl,  g_qsl);
    cudaGetSymbolAddress((void**)&ksh,  g_ksh);
    cudaGetSymbolAddress((void**)&ksl,  g_ksl);
    cudaGetSymbolAddress((void**)&vth,  g_vth);
    cudaGetSymbolAddress((void**)&vtl,  g_vtl);

    const int M = BB * SS;   // 4096
    const int G2_SMEM = 2 * G2_STAGE;  // 61440

    // 0) RoPE table (fp64 rotation recurrence)
    rope_table_kernel<<<8, 256>>>();

    // 1) bf16 splits of x and weights (MLP=4: grid = n4/1024)
    {
        int n4x = M * DD / 4;
        split_bf16_kernel<<<n4x / 1024, 256>>>(x, xh, xl, n4x);
        int n4q = DD * DD / 4;
        split_bf16_kernel<<<n4q / 1024, 256>>>(qw, qwh, qwl, n4q);
        int n4kv = 2 * DH * DD / 4;
        split_bf16_kernel<<<n4kv / 1024, 256>>>(kvw, kvwh, kvwl, n4kv);
        int n4o = DD * DD / 4;
        split_bf16_kernel<<<n4o / 1024, 256>>>(ow, owh, owl, n4o);
    }

    // 2) Fused Q+KV projection (tensor cores): N = 2048 + 256 = 2304
    cudaFuncSetAttribute(gemm_mma2, cudaFuncAttributeMaxDynamicSharedMemorySize, G2_SMEM);
    gemm_mma2<<<dim3((DD + 256) / 256, M / 128), 256, G2_SMEM>>>(
        xh, xl, qwh, qwl, kvwh, kvwl, qb, kvb, q_buf, kv_buf, M, DD, DD);

    // 3) Fused rope + attention operand splits
    {
        int nq = BB * SS * HH * 16;          // 1M threads
        rope_split_q_kernel<<<nq / 256, 256>>>(q_buf, qsh, qsl);
        int nk = BB * SS * 16;               // 64K threads
        rope_ksplit_kernel<<<nk / 256, 256>>>(kv_buf, ksh, ksl);
        vtsplit_kernel<<<dim3(SS / 32, DH / 32, BB), dim3(32, 8)>>>(kv_buf, vth, vtl);
    }

    // 4) Tensor-core causal MQA flash attention -> split bf16 output
    {
        cudaFuncSetAttribute(attn_mma, cudaFuncAttributeMaxDynamicSharedMemorySize, ATT_SMEM);
        attn_mma<<<dim3(SS / 128, HH, BB), 256, ATT_SMEM>>>(qsh, qsl, ksh, ksl,
                                                            vth, vtl, ath, atl);
    }

    // 5) Output projection (tensor cores): N = 2048 (q-segment covers all)
    gemm_mma2<<<dim3(DD / 256, M / 128), 256, G2_SMEM>>>(
        ath, atl, owh, owl, owh, owl, ob, ob, out, out, M, DD, DD);
}